// round 15
// baseline (speedup 1.0000x reference)
#include <cuda_runtime.h>
#include <cuda_bf16.h>

#define S_LEN 2048
#define D_MODEL 4096
#define NH 32
#define DHD 128
#define QLR_ 1536
#define OLR_ 512
#define NG 4
#define KSPLIT 8
#define QRSPLIT 4
#define QK_SCALE 0.08838834764831845f

typedef __nv_bfloat16 bf16;

// ---------------- scratch (no allocation allowed -> device globals) ---------
__device__ float g_qrpart[QRSPLIT * S_LEN * QLR_];
__device__ float g_kvpart[KSPLIT * S_LEN * DHD];
__device__ float g_cs[S_LEN * 32 * 2];

__device__ bf16 g_qhi[S_LEN * NH * DHD], g_qlo[S_LEN * NH * DHD];
__device__ bf16 g_khi[S_LEN * DHD],      g_klo[S_LEN * DHD];
__device__ bf16 g_vthi[DHD * S_LEN],     g_vtlo[DHD * S_LEN];   // transposed V

__device__ bf16 g_hid_hi[S_LEN * D_MODEL],  g_hid_lo[S_LEN * D_MODEL];
__device__ bf16 g_wqa_hi[QLR_ * D_MODEL],   g_wqa_lo[QLR_ * D_MODEL];
__device__ bf16 g_wqb_hi[NH * DHD * QLR_],  g_wqb_lo[NH * DHD * QLR_];
__device__ bf16 g_wkv_hi[DHD * D_MODEL],    g_wkv_lo[DHD * D_MODEL];
__device__ bf16 g_qr_hi[S_LEN * QLR_],      g_qr_lo[S_LEN * QLR_];
__device__ bf16 g_attn_hi[S_LEN * NH * DHD],g_attn_lo[S_LEN * NH * DHD];
__device__ bf16 g_woa_hi[NG * OLR_ * 1024], g_woa_lo[NG * OLR_ * 1024];
__device__ bf16 g_low_hi[S_LEN * NG * OLR_],g_low_lo[S_LEN * NG * OLR_];
__device__ bf16 g_wob_hi[D_MODEL * NG * OLR_], g_wob_lo[D_MODEL * NG * OLR_];

// ---------------- bf16 split helpers ----------------------------------------
__device__ __forceinline__ void bf16_split1(float f, bf16& h, bf16& l)
{
    h = __float2bfloat16(f);
    l = __float2bfloat16(f - __bfloat162float(h));
}

__device__ __forceinline__ unsigned pack_split_bf16(float p0, float p1,
                                                    unsigned& lo)
{
    unsigned hi;
    asm("cvt.rn.bf16x2.f32 %0, %1, %2;" : "=r"(hi) : "f"(p1), "f"(p0));
    __nv_bfloat162 hb;
    *reinterpret_cast<unsigned*>(&hb) = hi;
    float h0 = __bfloat162float(hb.x), h1 = __bfloat162float(hb.y);
    asm("cvt.rn.bf16x2.f32 %0, %1, %2;" : "=r"(lo)
        : "f"(p1 - h1), "f"(p0 - h0));
    return hi;
}

// ---------------- one-launch segmented operand split ------------------------
struct SplitSeg { const float4* src; uint2* hi; uint2* lo; int n4; };
struct SplitArgs { SplitSeg seg[6]; };

__global__ void split_multi(SplitArgs a)
{
    const SplitSeg s = a.seg[blockIdx.y];
    int i = blockIdx.x * blockDim.x + threadIdx.x;
    if (i >= s.n4) return;
    float4 v = s.src[i];
    unsigned l01, l23;
    unsigned h01 = pack_split_bf16(v.x, v.y, l01);
    unsigned h23 = pack_split_bf16(v.z, v.w, l23);
    s.hi[i] = make_uint2(h01, h23);
    s.lo[i] = make_uint2(l01, l23);
}

// ---------------- cos/sin table (fp64 once) ---------------------------------
__global__ void cs_table_kernel(float* __restrict__ cs,
                                const void* __restrict__ pos_raw)
{
    const int s = blockIdx.x, d = threadIdx.x;
    const int* p32 = (const int*)pos_raw;
    long long p;
    if (p32[1] == 1) p = (long long)p32[s];
    else             p = ((const long long*)pos_raw)[s];
    const double inv = pow(10000.0, -(double)d / 32.0);
    const double ang = (double)p * inv;
    cs[(s * 32 + d) * 2 + 0] = (float)cos(ang);
    cs[(s * 32 + d) * 2 + 1] = (float)sin(ang);
}

// ============================================================================
// BF16 tensor-core GEMM (3-term split), k32 2-stage cp.async, ldmatrix.
// CTA 256x128x32, 8 warps (4M x 2N), warp tile 64x64 (fat tiles cut smem
// fragment traffic per MMA ~1.5x -> crossbar no longer binds). 1 CTA/SM.
// C[M,N] = A[M,K] @ B[N,K]^T. Optional epilogues: fp32 C, bf16 hi/lo split,
// fused RoPE+scale.
// ============================================================================
#define GPW 20                    // smem row stride in b32 words (16 data + 4)
#define A_ARRB (256 * GPW * 4)    // 20480 B per A array
#define B_ARRB (128 * GPW * 4)    // 10240 B per B array
#define STG_B (2 * A_ARRB + 2 * B_ARRB)  // 61440 B per stage
#define GEMM_SMEM (2 * STG_B)     // 122880 B

#define MMA_BF16(c, a, b)                                                  \
    asm volatile(                                                          \
        "mma.sync.aligned.m16n8k16.row.col.f32.bf16.bf16.f32 "             \
        "{%0,%1,%2,%3}, {%4,%5,%6,%7}, {%8,%9}, {%0,%1,%2,%3};"            \
        : "+f"((c)[0]), "+f"((c)[1]), "+f"((c)[2]), "+f"((c)[3])           \
        : "r"((a)[0]), "r"((a)[1]), "r"((a)[2]), "r"((a)[3]),              \
          "r"((b)[0]), "r"((b)[1]))

#define LDSM_X4(r, addr)                                                   \
    asm volatile("ldmatrix.sync.aligned.m8n8.x4.shared.b16 "               \
                 "{%0,%1,%2,%3}, [%4];"                                    \
                 : "=r"((r)[0]), "=r"((r)[1]), "=r"((r)[2]), "=r"((r)[3])  \
                 : "r"(addr))

#define CPA16(dst, src)                                                    \
    asm volatile("cp.async.cg.shared.global [%0], [%1], 16;"               \
                 :: "r"(dst), "l"(src))
#define CPA_COMMIT() asm volatile("cp.async.commit_group;" ::)
#define CPA_WAIT1()  asm volatile("cp.async.wait_group 1;" ::)

__global__ void __launch_bounds__(256, 1) gemm_bf16_pre(
    const bf16* __restrict__ Ahi, const bf16* __restrict__ Alo,
    int lda, long long sAz,
    const bf16* __restrict__ Bhi, const bf16* __restrict__ Blo,
    int ldb, long long sBz,
    float* __restrict__ C, bf16* __restrict__ Chi, bf16* __restrict__ Clo,
    int ldc, long long sCz,
    int K, int rope, const float* __restrict__ cst)
{
    extern __shared__ unsigned smw[];
    const size_t zo = (size_t)blockIdx.z;

    const int bm = blockIdx.y * 256;
    const int bn = blockIdx.x * 128;
    const int tid = threadIdx.x;
    const int wid = tid >> 5, lane = tid & 31;
    const int wm = wid >> 1, wn = wid & 1;    // 4 x 2 warp grid
    const int gid = lane >> 2, tig = lane & 3;

    // cp.async loader: rowbase = tid>>2, chunk = tid&3 (16B chunks)
    const int rowb = tid >> 2, chk = tid & 3;
    const bf16* gA = Ahi + zo * sAz + (size_t)(bm + rowb) * lda + chk * 8;
    const bf16* gB = Bhi + zo * sBz + (size_t)(bn + rowb) * ldb + chk * 8;
    const long long dA = Alo - Ahi;
    const long long dB = Blo - Bhi;

    const unsigned smem0 = (unsigned)__cvta_generic_to_shared(smw);
    const unsigned dsm = (unsigned)((rowb * GPW + chk * 4) * 4);
    const unsigned RJ = 64 * GPW * 4;   // 64-row block in smem bytes

    // ldmatrix per-thread byte offsets
    const int lane15 = lane & 15;
    const unsigned aoff = (unsigned)(((wm * 64 + lane15) * GPW
                          + ((lane >> 4) << 2)) * 4);
    const unsigned boff = (unsigned)(((wn * 64 + (lane & 7)
                          + ((lane >> 4) << 3)) * GPW
                          + (((lane >> 3) & 1) << 2)) * 4);

    float acc[4][8][4];
#pragma unroll
    for (int i = 0; i < 4; i++)
#pragma unroll
        for (int j = 0; j < 8; j++)
#pragma unroll
            for (int l = 0; l < 4; l++) acc[i][j][l] = 0.f;

#define ISSUE_TILE(stage, koff)                                            \
    do {                                                                   \
        unsigned b_ = smem0 + (stage) * STG_B;                             \
        _Pragma("unroll")                                                  \
        for (int j = 0; j < 4; j++) {                                      \
            CPA16(b_ + dsm + j * RJ, gA + j * 64 * lda + (koff));          \
            CPA16(b_ + A_ARRB + dsm + j * RJ,                              \
                  gA + dA + j * 64 * lda + (koff));                        \
        }                                                                  \
        _Pragma("unroll")                                                  \
        for (int j = 0; j < 2; j++) {                                      \
            CPA16(b_ + 2 * A_ARRB + dsm + j * RJ,                          \
                  gB + j * 64 * ldb + (koff));                             \
            CPA16(b_ + 2 * A_ARRB + B_ARRB + dsm + j * RJ,                 \
                  gB + dB + j * 64 * ldb + (koff));                        \
        }                                                                  \
    } while (0)

    const int T = K / 32;
    ISSUE_TILE(0, 0);
    CPA_COMMIT();
    ISSUE_TILE(1, 32);
    CPA_COMMIT();
    CPA_WAIT1();
    __syncthreads();

    for (int t = 0; t < T; t++) {
        const int s = t & 1;
        const unsigned base = smem0 + s * STG_B;
        const unsigned aH = base + aoff;
        const unsigned aL = aH + A_ARRB;
        const unsigned bH = base + 2 * A_ARRB + boff;
        const unsigned bL = bH + B_ARRB;

#pragma unroll
        for (int kk = 0; kk < 2; kk++) {
            const unsigned kb = kk * 32;
            unsigned ah[4][4], al[4][4], bh[4][4], bl[4][4];
#pragma unroll
            for (int mf = 0; mf < 4; mf++) {
                LDSM_X4(ah[mf], aH + mf * (16 * GPW * 4) + kb);
                LDSM_X4(al[mf], aL + mf * (16 * GPW * 4) + kb);
            }
#pragma unroll
            for (int p = 0; p < 4; p++) {
                LDSM_X4(bh[p], bH + p * (16 * GPW * 4) + kb);
                LDSM_X4(bl[p], bL + p * (16 * GPW * 4) + kb);
            }
#pragma unroll
            for (int mf = 0; mf < 4; mf++)
#pragma unroll
                for (int nf = 0; nf < 8; nf++) {
                    unsigned bfh[2] = { bh[nf >> 1][(nf & 1) * 2],
                                        bh[nf >> 1][(nf & 1) * 2 + 1] };
                    unsigned bfl[2] = { bl[nf >> 1][(nf & 1) * 2],
                                        bl[nf >> 1][(nf & 1) * 2 + 1] };
                    MMA_BF16(acc[mf][nf], ah[mf], bfh);
                    MMA_BF16(acc[mf][nf], al[mf], bfh);
                    MMA_BF16(acc[mf][nf], ah[mf], bfl);
                }
        }

        __syncthreads();
        if (t + 2 < T) ISSUE_TILE(s, (t + 2) * 32);
        CPA_COMMIT();
        CPA_WAIT1();
        __syncthreads();
    }

#pragma unroll
    for (int mf = 0; mf < 4; mf++) {
        const int row = bm + wm * 64 + mf * 16 + gid;
#pragma unroll
        for (int nf = 0; nf < 8; nf++) {
            const int col = bn + wn * 64 + nf * 8 + tig * 2;
            const size_t o0 = zo * sCz + (size_t)row * ldc + col;
            const size_t o1 = zo * sCz + (size_t)(row + 8) * ldc + col;
            float v0 = acc[mf][nf][0], v1 = acc[mf][nf][1];
            float w0 = acc[mf][nf][2], w1 = acc[mf][nf][3];
            if (rope) {
                const int dh = col & 127;
                if (dh >= 64) {
                    const int d = (dh - 64) >> 1;
                    const float c0 = cst[(row * 32 + d) * 2];
                    const float s0 = cst[(row * 32 + d) * 2 + 1];
                    const float c1 = cst[((row + 8) * 32 + d) * 2];
                    const float s1 = cst[((row + 8) * 32 + d) * 2 + 1];
                    float t0 = v0 * c0 - v1 * s0;
                    float t1 = v0 * s0 + v1 * c0;
                    v0 = t0; v1 = t1;
                    t0 = w0 * c1 - w1 * s1;
                    t1 = w0 * s1 + w1 * c1;
                    w0 = t0; w1 = t1;
                }
                v0 *= QK_SCALE; v1 *= QK_SCALE;
                w0 *= QK_SCALE; w1 *= QK_SCALE;
            }
            if (C) {
                *reinterpret_cast<float2*>(&C[o0]) = make_float2(v0, v1);
                *reinterpret_cast<float2*>(&C[o1]) = make_float2(w0, w1);
            }
            if (Chi) {
                unsigned lo0, lo1;
                unsigned hi0 = pack_split_bf16(v0, v1, lo0);
                unsigned hi1 = pack_split_bf16(w0, w1, lo1);
                *reinterpret_cast<unsigned*>(&Chi[o0]) = hi0;
                *reinterpret_cast<unsigned*>(&Clo[o0]) = lo0;
                *reinterpret_cast<unsigned*>(&Chi[o1]) = hi1;
                *reinterpret_cast<unsigned*>(&Clo[o1]) = lo1;
            }
        }
    }
#undef ISSUE_TILE
}

// ---------------- RMS norm (4 split-K partials) -> bf16 hi/lo ---------------
__global__ void rmsnorm_split4_kernel(const float* __restrict__ x,
                                      long long zstride,
                                      const float* __restrict__ g,
                                      bf16* __restrict__ xhi,
                                      bf16* __restrict__ xlo, int N)
{
    const int row = blockIdx.x;
    const float* r0 = x + (size_t)row * N;
    float ss = 0.f;
    for (int c = threadIdx.x; c < N; c += blockDim.x) {
        float v = r0[c] + r0[c + zstride] + r0[c + 2 * zstride]
                + r0[c + 3 * zstride];
        ss += v * v;
    }
#pragma unroll
    for (int o = 16; o; o >>= 1) ss += __shfl_xor_sync(0xFFFFFFFFu, ss, o);
    __shared__ float red[32];
    const int w = threadIdx.x >> 5, l = threadIdx.x & 31;
    if (l == 0) red[w] = ss;
    __syncthreads();
    if (threadIdx.x == 0) {
        float t = 0.f;
        int nw = blockDim.x >> 5;
        for (int i = 0; i < nw; i++) t += red[i];
        red[0] = rsqrtf(t / (float)N + 1e-6f);
    }
    __syncthreads();
    const float inv = red[0];
    for (int c = threadIdx.x; c < N; c += blockDim.x) {
        float v = (r0[c] + r0[c + zstride] + r0[c + 2 * zstride]
                 + r0[c + 3 * zstride]) * inv * g[c];
        bf16 h, lo;
        bf16_split1(v, h, lo);
        xhi[(size_t)row * N + c] = h;
        xlo[(size_t)row * N + c] = lo;
    }
}

// -- kv split-K reduce + rmsnorm + V^T split + fused RoPE-K split ------------
__global__ void kv_fused_kernel(const float* __restrict__ parts,
                                const float* __restrict__ g,
                                const float* __restrict__ cs,
                                bf16* __restrict__ khi, bf16* __restrict__ klo,
                                bf16* __restrict__ vthi, bf16* __restrict__ vtlo)
{
    const int row = blockIdx.x, tid = threadIdx.x;   // row = s, tid = d
    float x = 0.f;
#pragma unroll
    for (int z = 0; z < KSPLIT; z++)
        x += parts[(size_t)z * S_LEN * DHD + (size_t)row * DHD + tid];
    float ss = x * x;
#pragma unroll
    for (int o = 16; o; o >>= 1) ss += __shfl_xor_sync(0xFFFFFFFFu, ss, o);
    __shared__ float r4[4];
    if ((tid & 31) == 0) r4[tid >> 5] = ss;
    __syncthreads();
    const float tot = r4[0] + r4[1] + r4[2] + r4[3];
    const float v = x * rsqrtf(tot / (float)DHD + 1e-6f) * g[tid];

    bf16 h, l;
    bf16_split1(v, h, l);
    vthi[(size_t)tid * S_LEN + row] = h;
    vtlo[(size_t)tid * S_LEN + row] = l;

    const float partner = __shfl_xor_sync(0xFFFFFFFFu, v, 1);
    float kval = v;
    if (tid >= 64) {
        const int dd = (tid - 64) >> 1;
        const float c = cs[(row * 32 + dd) * 2 + 0];
        const float n = cs[(row * 32 + dd) * 2 + 1];
        kval = (tid & 1) ? (partner * n + v * c) : (v * c - partner * n);
    }
    bf16_split1(kval, h, l);
    khi[(size_t)row * DHD + tid] = h;
    klo[(size_t)row * DHD + tid] = l;
}

// ---------------- BF16 tensor-core flash attention with sink ----------------
// grid (S/64, NH), 256 threads (8 warps: 4 M x 2 N). 64q x 128k tiles.
// cp.async K/V pipelined, ldmatrix fragments, heavy q-tiles first.
#define QPW 68
#define VPW 68
#define PPW 68
#define ATTN_WORDS (2*64*QPW + 2*128*QPW + 2*128*VPW + 2*64*PPW + 256)
#define ATTN_SMEM (ATTN_WORDS * 4)   // 209920 B

__global__ void __launch_bounds__(256) attn_mma_kernel(
    const bf16* __restrict__ Qhi, const bf16* __restrict__ Qlo,
    const bf16* __restrict__ Khi, const bf16* __restrict__ Klo,
    const bf16* __restrict__ Vthi, const bf16* __restrict__ Vtlo,
    const float* __restrict__ sink,
    bf16* __restrict__ Ohi, bf16* __restrict__ Olo)
{
    extern __shared__ unsigned smw[];
    unsigned* Qh  = smw;
    unsigned* Ql  = Qh + 64 * QPW;
    unsigned* Kh  = Ql + 64 * QPW;
    unsigned* Kl  = Kh + 128 * QPW;
    unsigned* Vth = Kl + 128 * QPW;
    unsigned* Vtl = Vth + 128 * VPW;
    unsigned* Ph  = Vtl + 128 * VPW;
    unsigned* Pl  = Ph + 64 * PPW;
    float* smax = (float*)(Pl + 64 * PPW);
    float* ssum = smax + 128;

    const int h  = blockIdx.y;
    const int qt = gridDim.x - 1 - blockIdx.x;   // heavy tiles first
    const int q0 = qt * 64;
    const int tid = threadIdx.x;
    const int w = tid >> 5, lane = tid & 31;
    const int wm = w & 3, wn = w >> 2;
    const int g = lane >> 2, t = lane & 3;
    const int m0 = wm * 16;
    const int rA = m0 + g, rB = m0 + g + 8;

    const unsigned sQh = (unsigned)__cvta_generic_to_shared(Qh);
    const unsigned sQl = (unsigned)__cvta_generic_to_shared(Ql);
    const unsigned sKh = (unsigned)__cvta_generic_to_shared(Kh);
    const unsigned sKl = (unsigned)__cvta_generic_to_shared(Kl);
    const unsigned sVh = (unsigned)__cvta_generic_to_shared(Vth);
    const unsigned sVl = (unsigned)__cvta_generic_to_shared(Vtl);
    const unsigned sPh = (unsigned)__cvta_generic_to_shared(Ph);
    const unsigned sPl = (unsigned)__cvta_generic_to_shared(Pl);

    const int lane15 = lane & 15;
    const unsigned qoffA = (unsigned)(((m0 + lane15) * QPW
                           + ((lane >> 4) << 2)) * 4);
    const unsigned koffB = (unsigned)(((wn * 64 + (lane & 7)
                           + ((lane >> 4) << 3)) * QPW
                           + (((lane >> 3) & 1) << 2)) * 4);
    const unsigned poffA = (unsigned)(((m0 + lane15) * PPW
                           + ((lane >> 4) << 2)) * 4);
    const unsigned voffB = (unsigned)(((wn * 64 + (lane & 7)
                           + ((lane >> 4) << 3)) * VPW
                           + (((lane >> 3) & 1) << 2)) * 4);

#define AT_ISSUE_K(k0_)                                                    \
    for (int j = 0; j < 8; j++) {                                          \
        int idx = tid + j * 256;                                           \
        int r_ = idx >> 4, cq_ = idx & 15;                                 \
        unsigned so_ = (r_ * QPW + cq_ * 4) * 4;                           \
        size_t go_ = (size_t)((k0_) + r_) * DHD + cq_ * 8;                 \
        CPA16(sKh + so_, Khi + go_);                                       \
        CPA16(sKl + so_, Klo + go_);                                       \
    }
#define AT_ISSUE_V(k0_)                                                    \
    for (int j = 0; j < 8; j++) {                                          \
        int idx = tid + j * 256;                                           \
        int r_ = idx >> 4, cq_ = idx & 15;                                 \
        unsigned so_ = (r_ * VPW + cq_ * 4) * 4;                           \
        size_t go_ = (size_t)r_ * S_LEN + (k0_) + cq_ * 8;                 \
        CPA16(sVh + so_, Vthi + go_);                                      \
        CPA16(sVl + so_, Vtlo + go_);                                      \
    }

    for (int j = 0; j < 4; j++) {
        int idx = tid + j * 256;
        int r = idx >> 4, cq = idx & 15;
        unsigned so = (r * QPW + cq * 4) * 4;
        size_t go = ((size_t)(q0 + r) * NH + h) * DHD + cq * 8;
        CPA16(sQh + so, Qhi + go);
        CPA16(sQl + so, Qlo + go);
    }
    AT_ISSUE_K(0);
    CPA_COMMIT();
    AT_ISSUE_V(0);
    CPA_COMMIT();

    float mr0 = sink[h], mr1 = mr0, lr0 = 1.f, lr1 = 1.f;
    float oa[8][4];
#pragma unroll
    for (int i = 0; i < 8; i++)
#pragma unroll
        for (int j = 0; j < 4; j++) oa[i][j] = 0.f;

    const int NT = (q0 + 64 + 127) >> 7;   // 128-key tiles, causal
    for (int kt = 0; kt < NT; kt++) {
        const int k0 = kt * 128;
        CPA_WAIT1();
        __syncthreads();

        // ---- S = Q K^T over 128 keys ----
        float sa[8][4];
#pragma unroll
        for (int i = 0; i < 8; i++)
#pragma unroll
            for (int j = 0; j < 4; j++) sa[i][j] = 0.f;

#pragma unroll
        for (int ks = 0; ks < 8; ks++) {
            const unsigned kb = ks * 32;
            unsigned ah[4], al[4], kh[4][4], kl[4][4];
            LDSM_X4(ah, sQh + qoffA + kb);
            LDSM_X4(al, sQl + qoffA + kb);
#pragma unroll
            for (int p = 0; p < 4; p++) {
                LDSM_X4(kh[p], sKh + koffB + p * (16 * QPW * 4) + kb);
                LDSM_X4(kl[p], sKl + koffB + p * (16 * QPW * 4) + kb);
            }
#pragma unroll
            for (int nt = 0; nt < 8; nt++) {
                unsigned bh[2] = { kh[nt >> 1][(nt & 1) * 2],
                                   kh[nt >> 1][(nt & 1) * 2 + 1] };
                unsigned bl[2] = { kl[nt >> 1][(nt & 1) * 2],
                                   kl[nt >> 1][(nt & 1) * 2 + 1] };
                MMA_BF16(sa[nt], ah, bh);
                MMA_BF16(sa[nt], al, bh);
                MMA_BF16(sa[nt], ah, bl);
            }
        }

        // ---- causal mask ----
        const int qi0 = q0 + rA, qi1 = q0 + rB;
#pragma unroll
        for (int nt = 0; nt < 8; nt++) {
            const int kc0 = k0 + wn * 64 + nt * 8 + 2 * t;
            if (kc0     > qi0) sa[nt][0] = -1e30f;
            if (kc0 + 1 > qi0) sa[nt][1] = -1e30f;
            if (kc0     > qi1) sa[nt][2] = -1e30f;
            if (kc0 + 1 > qi1) sa[nt][3] = -1e30f;
        }

        // ---- row max ----
        float rm0 = -1e30f, rm1 = -1e30f;
#pragma unroll
        for (int nt = 0; nt < 8; nt++) {
            rm0 = fmaxf(rm0, fmaxf(sa[nt][0], sa[nt][1]));
            rm1 = fmaxf(rm1, fmaxf(sa[nt][2], sa[nt][3]));
        }
        rm0 = fmaxf(rm0, __shfl_xor_sync(0xFFFFFFFFu, rm0, 1));
        rm0 = fmaxf(rm0, __shfl_xor_sync(0xFFFFFFFFu, rm0, 2));
        rm1 = fmaxf(rm1, __shfl_xor_sync(0xFFFFFFFFu, rm1, 1));
        rm1 = fmaxf(rm1, __shfl_xor_sync(0xFFFFFFFFu, rm1, 2));
        if (t == 0) { smax[wn * 64 + rA] = rm0; smax[wn * 64 + rB] = rm1; }
        __syncthreads();

        const float mn0 = fmaxf(mr0, fmaxf(smax[rA], smax[64 + rA]));
        const float mn1 = fmaxf(mr1, fmaxf(smax[rB], smax[64 + rB]));
        const float alp0 = __expf(mr0 - mn0);
        const float alp1 = __expf(mr1 - mn1);
        mr0 = mn0; mr1 = mn1;

        // ---- p = exp(s - m), packed bf16 hi/lo P tile ----
        float ps0 = 0.f, ps1 = 0.f;
#pragma unroll
        for (int nt = 0; nt < 8; nt++) {
            float p0 = __expf(sa[nt][0] - mn0);
            float p1 = __expf(sa[nt][1] - mn0);
            float p2 = __expf(sa[nt][2] - mn1);
            float p3 = __expf(sa[nt][3] - mn1);
            ps0 += p0 + p1;
            ps1 += p2 + p3;
            const int pw = wn * 32 + nt * 4 + t;
            unsigned lo0, lo1;
            unsigned hi0 = pack_split_bf16(p0, p1, lo0);
            unsigned hi1 = pack_split_bf16(p2, p3, lo1);
            Ph[rA * PPW + pw] = hi0;  Pl[rA * PPW + pw] = lo0;
            Ph[rB * PPW + pw] = hi1;  Pl[rB * PPW + pw] = lo1;
        }
        ps0 += __shfl_xor_sync(0xFFFFFFFFu, ps0, 1);
        ps0 += __shfl_xor_sync(0xFFFFFFFFu, ps0, 2);
        ps1 += __shfl_xor_sync(0xFFFFFFFFu, ps1, 1);
        ps1 += __shfl_xor_sync(0xFFFFFFFFu, ps1, 2);
        if (t == 0) { ssum[wn * 64 + rA] = ps0; ssum[wn * 64 + rB] = ps1; }
        __syncthreads();   // K smem free after this point

        if (kt + 1 < NT) { AT_ISSUE_K(k0 + 128); }
        CPA_COMMIT();

        lr0 = lr0 * alp0 + ssum[rA] + ssum[64 + rA];
        lr1 = lr1 * alp1 + ssum[rB] + ssum[64 + rB];
#pragma unroll
        for (int nt = 0; nt < 8; nt++) {
            oa[nt][0] *= alp0; oa[nt][1] *= alp0;
            oa[nt][2] *= alp1; oa[nt][3] *= alp1;
        }

        CPA_WAIT1();
        __syncthreads();

        // ---- O += P V over 128 keys ----
#pragma unroll
        for (int ks = 0; ks < 8; ks++) {
            const unsigned kb = ks * 32;
            unsigned ph[4], pl[4];
            LDSM_X4(ph, sPh + poffA + kb);
            LDSM_X4(pl, sPl + poffA + kb);
#pragma unroll
            for (int ntp = 0; ntp < 4; ntp++) {
                unsigned vh[4], vl[4];
                LDSM_X4(vh, sVh + voffB + ntp * (16 * VPW * 4) + kb);
                LDSM_X4(vl, sVl + voffB + ntp * (16 * VPW * 4) + kb);
#pragma unroll
                for (int hf = 0; hf < 2; hf++) {
                    const int nt = ntp * 2 + hf;
                    unsigned bh[2] = { vh[hf * 2], vh[hf * 2 + 1] };
                    unsigned bl[2] = { vl[hf * 2], vl[hf * 2 + 1] };
                    MMA_BF16(oa[nt], ph, bh);
                    MMA_BF16(oa[nt], pl, bh);
                    MMA_BF16(oa[nt], ph, bl);
                }
            }
        }
        __syncthreads();
        if (kt + 1 < NT) { AT_ISSUE_V(k0 + 128); }
        CPA_COMMIT();
    }

    const float i0v = 1.f / lr0, i1v = 1.f / lr1;
#pragma unroll
    for (int nt = 0; nt < 8; nt++) {
        const int c = wn * 64 + nt * 8 + 2 * t;
        const size_t oA = ((size_t)(q0 + rA) * NH + h) * DHD + c;
        const size_t oB = ((size_t)(q0 + rB) * NH + h) * DHD + c;
        unsigned lo0, lo1;
        unsigned hi0 = pack_split_bf16(oa[nt][0] * i0v, oa[nt][1] * i0v, lo0);
        unsigned hi1 = pack_split_bf16(oa[nt][2] * i1v, oa[nt][3] * i1v, lo1);
        *reinterpret_cast<unsigned*>(&Ohi[oA]) = hi0;
        *reinterpret_cast<unsigned*>(&Olo[oA]) = lo0;
        *reinterpret_cast<unsigned*>(&Ohi[oB]) = hi1;
        *reinterpret_cast<unsigned*>(&Olo[oB]) = lo1;
    }
#undef AT_ISSUE_K
#undef AT_ISSUE_V
}

// ---------------- launch ----------------------------------------------------
extern "C" void kernel_launch(void* const* d_in, const int* in_sizes, int n_in,
                              void* d_out, int out_size)
{
    (void)in_sizes; (void)n_in; (void)out_size;
    const float* hidden = (const float*)d_in[0];
    const void*  pos    = d_in[1];
    const float* wq_a   = (const float*)d_in[2];
    const float* qng    = (const float*)d_in[3];
    const float* wq_b   = (const float*)d_in[4];
    const float* wkv    = (const float*)d_in[5];
    const float* kvng   = (const float*)d_in[6];
    const float* wo_a   = (const float*)d_in[7];
    const float* wo_b   = (const float*)d_in[8];
    const float* sink   = (const float*)d_in[9];
    float* out = (float*)d_out;

    float *qrpart, *kvpart, *cs;
    bf16 *qhi, *qlo, *khi, *klo, *vthi, *vtlo;
    bf16 *hid_hi, *hid_lo, *wqa_hi, *wqa_lo, *wqb_hi, *wqb_lo;
    bf16 *wkv_hi, *wkv_lo, *qr_hi, *qr_lo, *attn_hi, *attn_lo;
    bf16 *woa_hi, *woa_lo, *low_hi, *low_lo, *wob_hi, *wob_lo;
    cudaGetSymbolAddress((void**)&qrpart, g_qrpart);
    cudaGetSymbolAddress((void**)&kvpart, g_kvpart);
    cudaGetSymbolAddress((void**)&cs,  g_cs);
    cudaGetSymbolAddress((void**)&qhi, g_qhi);
    cudaGetSymbolAddress((void**)&qlo, g_qlo);
    cudaGetSymbolAddress((void**)&khi, g_khi);
    cudaGetSymbolAddress((void**)&klo, g_klo);
    cudaGetSymbolAddress((void**)&vthi, g_vthi);
    cudaGetSymbolAddress((void**)&vtlo, g_vtlo);
    cudaGetSymbolAddress((void**)&hid_hi, g_hid_hi);
    cudaGetSymbolAddress((void**)&hid_lo, g_hid_lo);
    cudaGetSymbolAddress((void**)&wqa_hi, g_wqa_hi);
    cudaGetSymbolAddress((void**)&wqa_lo, g_wqa_lo);
    cudaGetSymbolAddress((void**)&wqb_hi, g_wqb_hi);
    cudaGetSymbolAddress((void**)&wqb_lo, g_wqb_lo);
    cudaGetSymbolAddress((void**)&wkv_hi, g_wkv_hi);
    cudaGetSymbolAddress((void**)&wkv_lo, g_wkv_lo);
    cudaGetSymbolAddress((void**)&qr_hi,  g_qr_hi);
    cudaGetSymbolAddress((void**)&qr_lo,  g_qr_lo);
    cudaGetSymbolAddress((void**)&attn_hi, g_attn_hi);
    cudaGetSymbolAddress((void**)&attn_lo, g_attn_lo);
    cudaGetSymbolAddress((void**)&woa_hi, g_woa_hi);
    cudaGetSymbolAddress((void**)&woa_lo, g_woa_lo);
    cudaGetSymbolAddress((void**)&low_hi, g_low_hi);
    cudaGetSymbolAddress((void**)&low_lo, g_low_lo);
    cudaGetSymbolAddress((void**)&wob_hi, g_wob_hi);
    cudaGetSymbolAddress((void**)&wob_lo, g_wob_lo);

    cudaFuncSetAttribute(gemm_bf16_pre,
                         cudaFuncAttributeMaxDynamicSharedMemorySize, GEMM_SMEM);
    cudaFuncSetAttribute(attn_mma_kernel,
                         cudaFuncAttributeMaxDynamicSharedMemorySize, ATTN_SMEM);

    // 0) cos/sin table (fp64 once)
    cs_table_kernel<<<S_LEN, 32>>>(cs, pos);

    // 1) one-launch split of all static operands -> bf16 hi/lo
    SplitArgs sa;
    sa.seg[0] = { (const float4*)hidden, (uint2*)hid_hi, (uint2*)hid_lo,
                  S_LEN * D_MODEL / 4 };
    sa.seg[1] = { (const float4*)wq_a, (uint2*)wqa_hi, (uint2*)wqa_lo,
                  QLR_ * D_MODEL / 4 };
    sa.seg[2] = { (const float4*)wq_b, (uint2*)wqb_hi, (uint2*)wqb_lo,
                  NH * DHD * QLR_ / 4 };
    sa.seg[3] = { (const float4*)wkv, (uint2*)wkv_hi, (uint2*)wkv_lo,
                  DHD * D_MODEL / 4 };
    sa.seg[4] = { (const float4*)wo_a, (uint2*)woa_hi, (uint2*)woa_lo,
                  NG * OLR_ * 1024 / 4 };
    sa.seg[5] = { (const float4*)wo_b, (uint2*)wob_hi, (uint2*)wob_lo,
                  D_MODEL * NG * OLR_ / 4 };
    split_multi<<<dim3((S_LEN * D_MODEL / 4 + 255) / 256, 6), 256>>>(sa);

    // 2) kv partials (split-K by 8), BM=256
    gemm_bf16_pre<<<dim3(1, S_LEN / 256, KSPLIT), 256, GEMM_SMEM>>>(
        hid_hi, hid_lo, D_MODEL, D_MODEL / KSPLIT,
        wkv_hi, wkv_lo, D_MODEL, D_MODEL / KSPLIT,
        kvpart, nullptr, nullptr, DHD, (long long)S_LEN * DHD,
        D_MODEL / KSPLIT, 0, nullptr);
    // 3) qr partials (split-K by 4)
    gemm_bf16_pre<<<dim3(QLR_ / 128, S_LEN / 256, QRSPLIT), 256, GEMM_SMEM>>>(
        hid_hi, hid_lo, D_MODEL, D_MODEL / QRSPLIT,
        wqa_hi, wqa_lo, D_MODEL, D_MODEL / QRSPLIT,
        qrpart, nullptr, nullptr, QLR_, (long long)S_LEN * QLR_,
        D_MODEL / QRSPLIT, 0, nullptr);
    // 4) rms_norm(sum of 4 partials) -> qr_hi/qr_lo
    rmsnorm_split4_kernel<<<S_LEN, 256>>>(
        qrpart, (long long)S_LEN * QLR_, qng, qr_hi, qr_lo, QLR_);
    // 5) q = qr @ wq_b^T with fused RoPE+scale+split -> qhi/qlo
    gemm_bf16_pre<<<dim3((NH * DHD) / 128, S_LEN / 256, 1), 256, GEMM_SMEM>>>(
        qr_hi, qr_lo, QLR_, 0, wqb_hi, wqb_lo, QLR_, 0,
        nullptr, qhi, qlo, NH * DHD, 0, QLR_, 1, cs);
    // 6) kv reduce + rmsnorm + V^T split + RoPE-K split (fused)
    kv_fused_kernel<<<S_LEN, DHD>>>(kvpart, kvng, cs, khi, klo, vthi, vtlo);
    // 7) attention -> attn_hi/attn_lo
    attn_mma_kernel<<<dim3(S_LEN / 64, NH), 256, ATTN_SMEM>>>(
        qhi, qlo, khi, klo, vthi, vtlo, sink, attn_hi, attn_lo);
    // 8) grouped wo_a -> low_hi/low_lo (fused bf16 split epilogue)
    gemm_bf16_pre<<<dim3(OLR_ / 128, S_LEN / 256, NG), 256, GEMM_SMEM>>>(
        attn_hi, attn_lo, NH * DHD, 1024,
        woa_hi, woa_lo, 1024, (long long)OLR_ * 1024,
        nullptr, low_hi, low_lo, NG * OLR_, OLR_, 1024, 0, nullptr);
    // 9) out = low @ wo_b^T
    gemm_bf16_pre<<<dim3(D_MODEL / 128, S_LEN / 256, 1), 256, GEMM_SMEM>>>(
        low_hi, low_lo, NG * OLR_, 0, wob_hi, wob_lo, NG * OLR_, 0,
        out, nullptr, nullptr, D_MODEL, 0, NG * OLR_, 0, nullptr);
}

// round 16
// speedup vs baseline: 1.5265x; 1.5265x over previous
#include <cuda_runtime.h>
#include <cuda_fp16.h>

#define S_LEN 2048
#define D_MODEL 4096
#define NH 32
#define DHD 128
#define QLR_ 1536
#define OLR_ 512
#define NG 4
#define KSPLIT 8
#define QRSPLIT 4
#define QK_SCALE 0.08838834764831845f

typedef __half hf;

// ---------------- scratch (no allocation allowed -> device globals) ---------
__device__ float g_qrpart[QRSPLIT * S_LEN * QLR_];
__device__ float g_kvpart[KSPLIT * S_LEN * DHD];
__device__ float g_cs[S_LEN * 32 * 2];

__device__ hf g_qhi[S_LEN * NH * DHD], g_qlo[S_LEN * NH * DHD];
__device__ hf g_khi[S_LEN * DHD];
__device__ hf g_vthi[DHD * S_LEN];                 // transposed V (1-term)

__device__ hf g_hid_hi[S_LEN * D_MODEL],  g_hid_lo[S_LEN * D_MODEL];
__device__ hf g_wqa_hi[QLR_ * D_MODEL];
__device__ hf g_wqb_hi[NH * DHD * QLR_];
__device__ hf g_wkv_hi[DHD * D_MODEL];
__device__ hf g_qr_hi[S_LEN * QLR_],      g_qr_lo[S_LEN * QLR_];
__device__ hf g_attn_hi[S_LEN * NH * DHD],g_attn_lo[S_LEN * NH * DHD];
__device__ hf g_woa_hi[NG * OLR_ * 1024];
__device__ hf g_low_hi[S_LEN * NG * OLR_],g_low_lo[S_LEN * NG * OLR_];
__device__ hf g_wob_hi[D_MODEL * NG * OLR_];

// ---------------- fp16 split helpers ----------------------------------------
__device__ __forceinline__ void f16_split1(float f, hf& h, hf& l)
{
    h = __float2half_rn(f);
    l = __float2half_rn(f - __half2float(h));
}

__device__ __forceinline__ unsigned pack_split_f16(float p0, float p1,
                                                   unsigned& lo)
{
    unsigned hi;
    asm("cvt.rn.f16x2.f32 %0, %1, %2;" : "=r"(hi) : "f"(p1), "f"(p0));
    __half2 hb = *reinterpret_cast<__half2*>(&hi);
    float h0 = __half2float(__low2half(hb));
    float h1 = __half2float(__high2half(hb));
    asm("cvt.rn.f16x2.f32 %0, %1, %2;" : "=r"(lo)
        : "f"(p1 - h1), "f"(p0 - h0));
    return hi;
}

__device__ __forceinline__ unsigned pack_f16(float p0, float p1)
{
    unsigned hi;
    asm("cvt.rn.f16x2.f32 %0, %1, %2;" : "=r"(hi) : "f"(p1), "f"(p0));
    return hi;
}

// ---------------- one-launch segmented operand split ------------------------
// mode 0: 2-term (hi+lo); mode 1: 1-term (hi only, lo ignored)
struct SplitSeg { const float4* src; uint2* hi; uint2* lo; int n4; int mode; };
struct SplitArgs { SplitSeg seg[6]; };

__global__ void split_multi(SplitArgs a)
{
    const SplitSeg s = a.seg[blockIdx.y];
    int i = blockIdx.x * blockDim.x + threadIdx.x;
    if (i >= s.n4) return;
    float4 v = s.src[i];
    if (s.mode == 0) {
        unsigned l01, l23;
        unsigned h01 = pack_split_f16(v.x, v.y, l01);
        unsigned h23 = pack_split_f16(v.z, v.w, l23);
        s.hi[i] = make_uint2(h01, h23);
        s.lo[i] = make_uint2(l01, l23);
    } else {
        s.hi[i] = make_uint2(pack_f16(v.x, v.y), pack_f16(v.z, v.w));
    }
}

// ---------------- cos/sin table (fp64 once) ---------------------------------
__global__ void cs_table_kernel(float* __restrict__ cs,
                                const void* __restrict__ pos_raw)
{
    const int s = blockIdx.x, d = threadIdx.x;
    const int* p32 = (const int*)pos_raw;
    long long p;
    if (p32[1] == 1) p = (long long)p32[s];
    else             p = ((const long long*)pos_raw)[s];
    const double inv = pow(10000.0, -(double)d / 32.0);
    const double ang = (double)p * inv;
    cs[(s * 32 + d) * 2 + 0] = (float)cos(ang);
    cs[(s * 32 + d) * 2 + 1] = (float)sin(ang);
}

// ============================================================================
// FP16 tensor-core GEMM, 2-term split (A = hi+lo fp16, B = hi fp16 only).
// k32 2-stage cp.async, ldmatrix. C[M,N] = A[M,K] @ B[N,K]^T.
// CTA 128x128x32, 8 warps (2x4), m16n8k16. 2 MMAs per (frag, term-pair).
// Optional epilogues: fp32 C, f16 hi/lo split (Chi/Clo), fused RoPE+scale.
// ============================================================================
#define GPW 20                    // smem row stride in b32 words (16 data + 4)
#define GAW (128 * GPW)           // words per array
#define GEMM_SMEM (2 * 3 * GAW * 4)   // 61440 B (Ah|Al|Bh per stage)

#define MMA_F16(c, a, b)                                                   \
    asm volatile(                                                          \
        "mma.sync.aligned.m16n8k16.row.col.f32.f16.f16.f32 "               \
        "{%0,%1,%2,%3}, {%4,%5,%6,%7}, {%8,%9}, {%0,%1,%2,%3};"            \
        : "+f"((c)[0]), "+f"((c)[1]), "+f"((c)[2]), "+f"((c)[3])           \
        : "r"((a)[0]), "r"((a)[1]), "r"((a)[2]), "r"((a)[3]),              \
          "r"((b)[0]), "r"((b)[1]))

#define LDSM_X4(r, addr)                                                   \
    asm volatile("ldmatrix.sync.aligned.m8n8.x4.shared.b16 "               \
                 "{%0,%1,%2,%3}, [%4];"                                    \
                 : "=r"((r)[0]), "=r"((r)[1]), "=r"((r)[2]), "=r"((r)[3])  \
                 : "r"(addr))

#define CPA16(dst, src)                                                    \
    asm volatile("cp.async.cg.shared.global [%0], [%1], 16;"               \
                 :: "r"(dst), "l"(src))
#define CPA_COMMIT() asm volatile("cp.async.commit_group;" ::)
#define CPA_WAIT1()  asm volatile("cp.async.wait_group 1;" ::)

__global__ void __launch_bounds__(256, 2) gemm_f16_pre(
    const hf* __restrict__ Ahi, const hf* __restrict__ Alo,
    int lda, long long sAz,
    const hf* __restrict__ Bhi,
    int ldb, long long sBz,
    float* __restrict__ C, hf* __restrict__ Chi, hf* __restrict__ Clo,
    int ldc, long long sCz,
    int K, int rope, const float* __restrict__ cst)
{
    extern __shared__ unsigned smw[];
    const size_t zo = (size_t)blockIdx.z;

    const int bm = blockIdx.y * 128;
    const int bn = blockIdx.x * 128;
    const int tid = threadIdx.x;
    const int wid = tid >> 5, lane = tid & 31;
    const int wm = wid & 1, wn = wid >> 1;
    const int gid = lane >> 2, tig = lane & 3;

    const int i0 = tid, i1 = tid + 256;
    const int r0 = i0 >> 2, c0q = i0 & 3;
    const int r1 = i1 >> 2, c1q = i1 & 3;
    const hf* gA0 = Ahi + zo * sAz + (size_t)(bm + r0) * lda + c0q * 8;
    const hf* gA1 = Ahi + zo * sAz + (size_t)(bm + r1) * lda + c1q * 8;
    const hf* gB0 = Bhi + zo * sBz + (size_t)(bn + r0) * ldb + c0q * 8;
    const hf* gB1 = Bhi + zo * sBz + (size_t)(bn + r1) * ldb + c1q * 8;
    const long long dA = Alo - Ahi;

    const unsigned smem0 = (unsigned)__cvta_generic_to_shared(smw);
    const unsigned d0 = (r0 * GPW + c0q * 4) * 4;
    const unsigned d1 = (r1 * GPW + c1q * 4) * 4;
    const unsigned ARR = GAW * 4;

    const int lane15 = lane & 15;
    const unsigned aoff = (unsigned)(((wm * 64 + lane15) * GPW
                          + ((lane >> 4) << 2)) * 4);
    const unsigned boff = (unsigned)(((wn * 32 + (lane & 7)
                          + ((lane >> 4) << 3)) * GPW
                          + (((lane >> 3) & 1) << 2)) * 4);

    float acc[4][4][4];
#pragma unroll
    for (int i = 0; i < 4; i++)
#pragma unroll
        for (int j = 0; j < 4; j++)
#pragma unroll
            for (int l = 0; l < 4; l++) acc[i][j][l] = 0.f;

#define ISSUE_TILE(stage, koff)                                            \
    do {                                                                   \
        unsigned b_ = smem0 + (stage) * 3 * ARR;                           \
        CPA16(b_ + 0 * ARR + d0, gA0 + (koff));                            \
        CPA16(b_ + 0 * ARR + d1, gA1 + (koff));                            \
        CPA16(b_ + 1 * ARR + d0, gA0 + dA + (koff));                       \
        CPA16(b_ + 1 * ARR + d1, gA1 + dA + (koff));                       \
        CPA16(b_ + 2 * ARR + d0, gB0 + (koff));                            \
        CPA16(b_ + 2 * ARR + d1, gB1 + (koff));                            \
    } while (0)

    const int T = K / 32;
    ISSUE_TILE(0, 0);
    CPA_COMMIT();
    ISSUE_TILE(1, 32);
    CPA_COMMIT();
    CPA_WAIT1();
    __syncthreads();

    for (int t = 0; t < T; t++) {
        const int s = t & 1;
        const unsigned base = smem0 + s * 3 * ARR;
        const unsigned aH = base + aoff;
        const unsigned aL = aH + ARR;
        const unsigned bH = base + 2 * ARR + boff;

#pragma unroll
        for (int kk = 0; kk < 2; kk++) {
            const unsigned kb = kk * 32;
            unsigned ah[4][4], al[4][4], bh[2][4];
#pragma unroll
            for (int mf = 0; mf < 4; mf++) {
                LDSM_X4(ah[mf], aH + mf * (16 * GPW * 4) + kb);
                LDSM_X4(al[mf], aL + mf * (16 * GPW * 4) + kb);
            }
#pragma unroll
            for (int p = 0; p < 2; p++)
                LDSM_X4(bh[p], bH + p * (16 * GPW * 4) + kb);
#pragma unroll
            for (int mf = 0; mf < 4; mf++)
#pragma unroll
                for (int nf = 0; nf < 4; nf++) {
                    unsigned bfh[2] = { bh[nf >> 1][(nf & 1) * 2],
                                        bh[nf >> 1][(nf & 1) * 2 + 1] };
                    MMA_F16(acc[mf][nf], ah[mf], bfh);
                    MMA_F16(acc[mf][nf], al[mf], bfh);
                }
        }

        __syncthreads();
        if (t + 2 < T) ISSUE_TILE(s, (t + 2) * 32);
        CPA_COMMIT();
        CPA_WAIT1();
        __syncthreads();
    }

#pragma unroll
    for (int mf = 0; mf < 4; mf++) {
        const int row = bm + wm * 64 + mf * 16 + gid;
#pragma unroll
        for (int nf = 0; nf < 4; nf++) {
            const int col = bn + wn * 32 + nf * 8 + tig * 2;
            const size_t o0 = zo * sCz + (size_t)row * ldc + col;
            const size_t o1 = zo * sCz + (size_t)(row + 8) * ldc + col;
            float v0 = acc[mf][nf][0], v1 = acc[mf][nf][1];
            float w0 = acc[mf][nf][2], w1 = acc[mf][nf][3];
            if (rope) {
                const int dh = col & 127;
                if (dh >= 64) {
                    const int d = (dh - 64) >> 1;
                    const float c0 = cst[(row * 32 + d) * 2];
                    const float s0 = cst[(row * 32 + d) * 2 + 1];
                    const float c1 = cst[((row + 8) * 32 + d) * 2];
                    const float s1 = cst[((row + 8) * 32 + d) * 2 + 1];
                    float t0 = v0 * c0 - v1 * s0;
                    float t1 = v0 * s0 + v1 * c0;
                    v0 = t0; v1 = t1;
                    t0 = w0 * c1 - w1 * s1;
                    t1 = w0 * s1 + w1 * c1;
                    w0 = t0; w1 = t1;
                }
                v0 *= QK_SCALE; v1 *= QK_SCALE;
                w0 *= QK_SCALE; w1 *= QK_SCALE;
            }
            if (C) {
                *reinterpret_cast<float2*>(&C[o0]) = make_float2(v0, v1);
                *reinterpret_cast<float2*>(&C[o1]) = make_float2(w0, w1);
            }
            if (Chi) {
                unsigned lo0, lo1;
                unsigned hi0 = pack_split_f16(v0, v1, lo0);
                unsigned hi1 = pack_split_f16(w0, w1, lo1);
                *reinterpret_cast<unsigned*>(&Chi[o0]) = hi0;
                *reinterpret_cast<unsigned*>(&Clo[o0]) = lo0;
                *reinterpret_cast<unsigned*>(&Chi[o1]) = hi1;
                *reinterpret_cast<unsigned*>(&Clo[o1]) = lo1;
            }
        }
    }
#undef ISSUE_TILE
}

// ---------------- RMS norm (4 split-K partials) -> f16 hi/lo ----------------
__global__ void rmsnorm_split4_kernel(const float* __restrict__ x,
                                      long long zstride,
                                      const float* __restrict__ g,
                                      hf* __restrict__ xhi,
                                      hf* __restrict__ xlo, int N)
{
    const int row = blockIdx.x;
    const float* r0 = x + (size_t)row * N;
    float ss = 0.f;
    for (int c = threadIdx.x; c < N; c += blockDim.x) {
        float v = r0[c] + r0[c + zstride] + r0[c + 2 * zstride]
                + r0[c + 3 * zstride];
        ss += v * v;
    }
#pragma unroll
    for (int o = 16; o; o >>= 1) ss += __shfl_xor_sync(0xFFFFFFFFu, ss, o);
    __shared__ float red[32];
    const int w = threadIdx.x >> 5, l = threadIdx.x & 31;
    if (l == 0) red[w] = ss;
    __syncthreads();
    if (threadIdx.x == 0) {
        float t = 0.f;
        int nw = blockDim.x >> 5;
        for (int i = 0; i < nw; i++) t += red[i];
        red[0] = rsqrtf(t / (float)N + 1e-6f);
    }
    __syncthreads();
    const float inv = red[0];
    for (int c = threadIdx.x; c < N; c += blockDim.x) {
        float v = (r0[c] + r0[c + zstride] + r0[c + 2 * zstride]
                 + r0[c + 3 * zstride]) * inv * g[c];
        hf h, lo;
        f16_split1(v, h, lo);
        xhi[(size_t)row * N + c] = h;
        xlo[(size_t)row * N + c] = lo;
    }
}

// -- kv split-K reduce + rmsnorm + V^T (1-term) + fused RoPE-K (1-term) ------
__global__ void kv_fused_kernel(const float* __restrict__ parts,
                                const float* __restrict__ g,
                                const float* __restrict__ cs,
                                hf* __restrict__ khi,
                                hf* __restrict__ vthi)
{
    const int row = blockIdx.x, tid = threadIdx.x;   // row = s, tid = d
    float x = 0.f;
#pragma unroll
    for (int z = 0; z < KSPLIT; z++)
        x += parts[(size_t)z * S_LEN * DHD + (size_t)row * DHD + tid];
    float ss = x * x;
#pragma unroll
    for (int o = 16; o; o >>= 1) ss += __shfl_xor_sync(0xFFFFFFFFu, ss, o);
    __shared__ float r4[4];
    if ((tid & 31) == 0) r4[tid >> 5] = ss;
    __syncthreads();
    const float tot = r4[0] + r4[1] + r4[2] + r4[3];
    const float v = x * rsqrtf(tot / (float)DHD + 1e-6f) * g[tid];

    vthi[(size_t)tid * S_LEN + row] = __float2half_rn(v);

    const float partner = __shfl_xor_sync(0xFFFFFFFFu, v, 1);
    float kval = v;
    if (tid >= 64) {
        const int dd = (tid - 64) >> 1;
        const float c = cs[(row * 32 + dd) * 2 + 0];
        const float n = cs[(row * 32 + dd) * 2 + 1];
        kval = (tid & 1) ? (partner * n + v * c) : (v * c - partner * n);
    }
    khi[(size_t)row * DHD + tid] = __float2half_rn(kval);
}

// ---------------- FP16 tensor-core flash attention with sink ----------------
// grid (S/64, NH), 256 threads (8 warps: 4 M x 2 N). 64q x 128k tiles.
// Q,P = 2-term fp16; K,V = 1-term. cp.async pipelined, heavy tiles first.
#define QPW 68
#define VPW 68
#define PPW 68
#define ATTN_WORDS (2*64*QPW + 128*QPW + 128*VPW + 2*64*PPW + 256)
#define ATTN_SMEM (ATTN_WORDS * 4)   // 140,288 B

__global__ void __launch_bounds__(256) attn_mma_kernel(
    const hf* __restrict__ Qhi, const hf* __restrict__ Qlo,
    const hf* __restrict__ Khi,
    const hf* __restrict__ Vthi,
    const float* __restrict__ sink,
    hf* __restrict__ Ohi, hf* __restrict__ Olo)
{
    extern __shared__ unsigned smw[];
    unsigned* Qh  = smw;
    unsigned* Ql  = Qh + 64 * QPW;
    unsigned* Kh  = Ql + 64 * QPW;
    unsigned* Vth = Kh + 128 * QPW;
    unsigned* Ph  = Vth + 128 * VPW;
    unsigned* Pl  = Ph + 64 * PPW;
    float* smax = (float*)(Pl + 64 * PPW);
    float* ssum = smax + 128;

    const int h  = blockIdx.y;
    const int qt = gridDim.x - 1 - blockIdx.x;   // heavy tiles first
    const int q0 = qt * 64;
    const int tid = threadIdx.x;
    const int w = tid >> 5, lane = tid & 31;
    const int wm = w & 3, wn = w >> 2;
    const int g = lane >> 2, t = lane & 3;
    const int m0 = wm * 16;
    const int rA = m0 + g, rB = m0 + g + 8;

    const unsigned sQh = (unsigned)__cvta_generic_to_shared(Qh);
    const unsigned sQl = (unsigned)__cvta_generic_to_shared(Ql);
    const unsigned sKh = (unsigned)__cvta_generic_to_shared(Kh);
    const unsigned sVh = (unsigned)__cvta_generic_to_shared(Vth);
    const unsigned sPh = (unsigned)__cvta_generic_to_shared(Ph);
    const unsigned sPl = (unsigned)__cvta_generic_to_shared(Pl);

    const int lane15 = lane & 15;
    const unsigned qoffA = (unsigned)(((m0 + lane15) * QPW
                           + ((lane >> 4) << 2)) * 4);
    const unsigned koffB = (unsigned)(((wn * 64 + (lane & 7)
                           + ((lane >> 4) << 3)) * QPW
                           + (((lane >> 3) & 1) << 2)) * 4);
    const unsigned poffA = (unsigned)(((m0 + lane15) * PPW
                           + ((lane >> 4) << 2)) * 4);
    const unsigned voffB = (unsigned)(((wn * 64 + (lane & 7)
                           + ((lane >> 4) << 3)) * VPW
                           + (((lane >> 3) & 1) << 2)) * 4);

#define AT_ISSUE_K(k0_)                                                    \
    for (int j = 0; j < 8; j++) {                                          \
        int idx = tid + j * 256;                                           \
        int r_ = idx >> 4, cq_ = idx & 15;                                 \
        unsigned so_ = (r_ * QPW + cq_ * 4) * 4;                           \
        size_t go_ = (size_t)((k0_) + r_) * DHD + cq_ * 8;                 \
        CPA16(sKh + so_, Khi + go_);                                       \
    }
#define AT_ISSUE_V(k0_)                                                    \
    for (int j = 0; j < 8; j++) {                                          \
        int idx = tid + j * 256;                                           \
        int r_ = idx >> 4, cq_ = idx & 15;                                 \
        unsigned so_ = (r_ * VPW + cq_ * 4) * 4;                           \
        size_t go_ = (size_t)r_ * S_LEN + (k0_) + cq_ * 8;                 \
        CPA16(sVh + so_, Vthi + go_);                                      \
    }

    for (int j = 0; j < 4; j++) {
        int idx = tid + j * 256;
        int r = idx >> 4, cq = idx & 15;
        unsigned so = (r * QPW + cq * 4) * 4;
        size_t go = ((size_t)(q0 + r) * NH + h) * DHD + cq * 8;
        CPA16(sQh + so, Qhi + go);
        CPA16(sQl + so, Qlo + go);
    }
    AT_ISSUE_K(0);
    CPA_COMMIT();
    AT_ISSUE_V(0);
    CPA_COMMIT();

    float mr0 = sink[h], mr1 = mr0, lr0 = 1.f, lr1 = 1.f;
    float oa[8][4];
#pragma unroll
    for (int i = 0; i < 8; i++)
#pragma unroll
        for (int j = 0; j < 4; j++) oa[i][j] = 0.f;

    const int NT = (q0 + 64 + 127) >> 7;   // 128-key tiles, causal
    for (int kt = 0; kt < NT; kt++) {
        const int k0 = kt * 128;
        CPA_WAIT1();
        __syncthreads();

        // ---- S = Q K^T over 128 keys (Q 2-term, K 1-term) ----
        float sa[8][4];
#pragma unroll
        for (int i = 0; i < 8; i++)
#pragma unroll
            for (int j = 0; j < 4; j++) sa[i][j] = 0.f;

#pragma unroll
        for (int ks = 0; ks < 8; ks++) {
            const unsigned kb = ks * 32;
            unsigned ah[4], al[4], kh[4][4];
            LDSM_X4(ah, sQh + qoffA + kb);
            LDSM_X4(al, sQl + qoffA + kb);
#pragma unroll
            for (int p = 0; p < 4; p++)
                LDSM_X4(kh[p], sKh + koffB + p * (16 * QPW * 4) + kb);
#pragma unroll
            for (int nt = 0; nt < 8; nt++) {
                unsigned bh[2] = { kh[nt >> 1][(nt & 1) * 2],
                                   kh[nt >> 1][(nt & 1) * 2 + 1] };
                MMA_F16(sa[nt], ah, bh);
                MMA_F16(sa[nt], al, bh);
            }
        }

        // ---- causal mask ----
        const int qi0 = q0 + rA, qi1 = q0 + rB;
#pragma unroll
        for (int nt = 0; nt < 8; nt++) {
            const int kc0 = k0 + wn * 64 + nt * 8 + 2 * t;
            if (kc0     > qi0) sa[nt][0] = -1e30f;
            if (kc0 + 1 > qi0) sa[nt][1] = -1e30f;
            if (kc0     > qi1) sa[nt][2] = -1e30f;
            if (kc0 + 1 > qi1) sa[nt][3] = -1e30f;
        }

        // ---- row max ----
        float rm0 = -1e30f, rm1 = -1e30f;
#pragma unroll
        for (int nt = 0; nt < 8; nt++) {
            rm0 = fmaxf(rm0, fmaxf(sa[nt][0], sa[nt][1]));
            rm1 = fmaxf(rm1, fmaxf(sa[nt][2], sa[nt][3]));
        }
        rm0 = fmaxf(rm0, __shfl_xor_sync(0xFFFFFFFFu, rm0, 1));
        rm0 = fmaxf(rm0, __shfl_xor_sync(0xFFFFFFFFu, rm0, 2));
        rm1 = fmaxf(rm1, __shfl_xor_sync(0xFFFFFFFFu, rm1, 1));
        rm1 = fmaxf(rm1, __shfl_xor_sync(0xFFFFFFFFu, rm1, 2));
        if (t == 0) { smax[wn * 64 + rA] = rm0; smax[wn * 64 + rB] = rm1; }
        __syncthreads();

        const float mn0 = fmaxf(mr0, fmaxf(smax[rA], smax[64 + rA]));
        const float mn1 = fmaxf(mr1, fmaxf(smax[rB], smax[64 + rB]));
        const float alp0 = __expf(mr0 - mn0);
        const float alp1 = __expf(mr1 - mn1);
        mr0 = mn0; mr1 = mn1;

        // ---- p = exp(s - m), packed f16 hi/lo P tile ----
        float ps0 = 0.f, ps1 = 0.f;
#pragma unroll
        for (int nt = 0; nt < 8; nt++) {
            float p0 = __expf(sa[nt][0] - mn0);
            float p1 = __expf(sa[nt][1] - mn0);
            float p2 = __expf(sa[nt][2] - mn1);
            float p3 = __expf(sa[nt][3] - mn1);
            ps0 += p0 + p1;
            ps1 += p2 + p3;
            const int pw = wn * 32 + nt * 4 + t;
            unsigned lo0, lo1;
            unsigned hi0 = pack_split_f16(p0, p1, lo0);
            unsigned hi1 = pack_split_f16(p2, p3, lo1);
            Ph[rA * PPW + pw] = hi0;  Pl[rA * PPW + pw] = lo0;
            Ph[rB * PPW + pw] = hi1;  Pl[rB * PPW + pw] = lo1;
        }
        ps0 += __shfl_xor_sync(0xFFFFFFFFu, ps0, 1);
        ps0 += __shfl_xor_sync(0xFFFFFFFFu, ps0, 2);
        ps1 += __shfl_xor_sync(0xFFFFFFFFu, ps1, 1);
        ps1 += __shfl_xor_sync(0xFFFFFFFFu, ps1, 2);
        if (t == 0) { ssum[wn * 64 + rA] = ps0; ssum[wn * 64 + rB] = ps1; }
        __syncthreads();   // K smem free after this point

        if (kt + 1 < NT) { AT_ISSUE_K(k0 + 128); }
        CPA_COMMIT();

        lr0 = lr0 * alp0 + ssum[rA] + ssum[64 + rA];
        lr1 = lr1 * alp1 + ssum[rB] + ssum[64 + rB];
#pragma unroll
        for (int nt = 0; nt < 8; nt++) {
            oa[nt][0] *= alp0; oa[nt][1] *= alp0;
            oa[nt][2] *= alp1; oa[nt][3] *= alp1;
        }

        CPA_WAIT1();
        __syncthreads();

        // ---- O += P V over 128 keys (P 2-term, V 1-term) ----
#pragma unroll
        for (int ks = 0; ks < 8; ks++) {
            const unsigned kb = ks * 32;
            unsigned ph[4], pl[4];
            LDSM_X4(ph, sPh + poffA + kb);
            LDSM_X4(pl, sPl + poffA + kb);
#pragma unroll
            for (int ntp = 0; ntp < 4; ntp++) {
                unsigned vh[4];
                LDSM_X4(vh, sVh + voffB + ntp * (16 * VPW * 4) + kb);
#pragma unroll
                for (int hfx = 0; hfx < 2; hfx++) {
                    const int nt = ntp * 2 + hfx;
                    unsigned bh[2] = { vh[hfx * 2], vh[hfx * 2 + 1] };
                    MMA_F16(oa[nt], ph, bh);
                    MMA_F16(oa[nt], pl, bh);
                }
            }
        }
        __syncthreads();
        if (kt + 1 < NT) { AT_ISSUE_V(k0 + 128); }
        CPA_COMMIT();
    }

    const float i0v = 1.f / lr0, i1v = 1.f / lr1;
#pragma unroll
    for (int nt = 0; nt < 8; nt++) {
        const int c = wn * 64 + nt * 8 + 2 * t;
        const size_t oA = ((size_t)(q0 + rA) * NH + h) * DHD + c;
        const size_t oB = ((size_t)(q0 + rB) * NH + h) * DHD + c;
        unsigned lo0, lo1;
        unsigned hi0 = pack_split_f16(oa[nt][0] * i0v, oa[nt][1] * i0v, lo0);
        unsigned hi1 = pack_split_f16(oa[nt][2] * i1v, oa[nt][3] * i1v, lo1);
        *reinterpret_cast<unsigned*>(&Ohi[oA]) = hi0;
        *reinterpret_cast<unsigned*>(&Olo[oA]) = lo0;
        *reinterpret_cast<unsigned*>(&Ohi[oB]) = hi1;
        *reinterpret_cast<unsigned*>(&Olo[oB]) = lo1;
    }
#undef AT_ISSUE_K
#undef AT_ISSUE_V
}

// ---------------- launch ----------------------------------------------------
extern "C" void kernel_launch(void* const* d_in, const int* in_sizes, int n_in,
                              void* d_out, int out_size)
{
    (void)in_sizes; (void)n_in; (void)out_size;
    const float* hidden = (const float*)d_in[0];
    const void*  pos    = d_in[1];
    const float* wq_a   = (const float*)d_in[2];
    const float* qng    = (const float*)d_in[3];
    const float* wq_b   = (const float*)d_in[4];
    const float* wkv    = (const float*)d_in[5];
    const float* kvng   = (const float*)d_in[6];
    const float* wo_a   = (const float*)d_in[7];
    const float* wo_b   = (const float*)d_in[8];
    const float* sink   = (const float*)d_in[9];
    float* out = (float*)d_out;

    float *qrpart, *kvpart, *cs;
    hf *qhi, *qlo, *khi, *vthi;
    hf *hid_hi, *hid_lo, *wqa_hi, *wqb_hi, *wkv_hi;
    hf *qr_hi, *qr_lo, *attn_hi, *attn_lo;
    hf *woa_hi, *low_hi, *low_lo, *wob_hi;
    cudaGetSymbolAddress((void**)&qrpart, g_qrpart);
    cudaGetSymbolAddress((void**)&kvpart, g_kvpart);
    cudaGetSymbolAddress((void**)&cs,  g_cs);
    cudaGetSymbolAddress((void**)&qhi, g_qhi);
    cudaGetSymbolAddress((void**)&qlo, g_qlo);
    cudaGetSymbolAddress((void**)&khi, g_khi);
    cudaGetSymbolAddress((void**)&vthi, g_vthi);
    cudaGetSymbolAddress((void**)&hid_hi, g_hid_hi);
    cudaGetSymbolAddress((void**)&hid_lo, g_hid_lo);
    cudaGetSymbolAddress((void**)&wqa_hi, g_wqa_hi);
    cudaGetSymbolAddress((void**)&wqb_hi, g_wqb_hi);
    cudaGetSymbolAddress((void**)&wkv_hi, g_wkv_hi);
    cudaGetSymbolAddress((void**)&qr_hi,  g_qr_hi);
    cudaGetSymbolAddress((void**)&qr_lo,  g_qr_lo);
    cudaGetSymbolAddress((void**)&attn_hi, g_attn_hi);
    cudaGetSymbolAddress((void**)&attn_lo, g_attn_lo);
    cudaGetSymbolAddress((void**)&woa_hi, g_woa_hi);
    cudaGetSymbolAddress((void**)&low_hi, g_low_hi);
    cudaGetSymbolAddress((void**)&low_lo, g_low_lo);
    cudaGetSymbolAddress((void**)&wob_hi, g_wob_hi);

    cudaFuncSetAttribute(gemm_f16_pre,
                         cudaFuncAttributeMaxDynamicSharedMemorySize, GEMM_SMEM);
    cudaFuncSetAttribute(attn_mma_kernel,
                         cudaFuncAttributeMaxDynamicSharedMemorySize, ATTN_SMEM);

    // 0) cos/sin table (fp64 once)
    cs_table_kernel<<<S_LEN, 32>>>(cs, pos);

    // 1) one-launch split: activations 2-term, weights 1-term
    SplitArgs sa;
    sa.seg[0] = { (const float4*)hidden, (uint2*)hid_hi, (uint2*)hid_lo,
                  S_LEN * D_MODEL / 4, 0 };
    sa.seg[1] = { (const float4*)wq_a, (uint2*)wqa_hi, nullptr,
                  QLR_ * D_MODEL / 4, 1 };
    sa.seg[2] = { (const float4*)wq_b, (uint2*)wqb_hi, nullptr,
                  NH * DHD * QLR_ / 4, 1 };
    sa.seg[3] = { (const float4*)wkv, (uint2*)wkv_hi, nullptr,
                  DHD * D_MODEL / 4, 1 };
    sa.seg[4] = { (const float4*)wo_a, (uint2*)woa_hi, nullptr,
                  NG * OLR_ * 1024 / 4, 1 };
    sa.seg[5] = { (const float4*)wo_b, (uint2*)wob_hi, nullptr,
                  D_MODEL * NG * OLR_ / 4, 1 };
    split_multi<<<dim3((S_LEN * D_MODEL / 4 + 255) / 256, 6), 256>>>(sa);

    // 2) kv partials (split-K by 8)
    gemm_f16_pre<<<dim3(1, S_LEN / 128, KSPLIT), 256, GEMM_SMEM>>>(
        hid_hi, hid_lo, D_MODEL, D_MODEL / KSPLIT,
        wkv_hi, D_MODEL, D_MODEL / KSPLIT,
        kvpart, nullptr, nullptr, DHD, (long long)S_LEN * DHD,
        D_MODEL / KSPLIT, 0, nullptr);
    // 3) qr partials (split-K by 4)
    gemm_f16_pre<<<dim3(QLR_ / 128, S_LEN / 128, QRSPLIT), 256, GEMM_SMEM>>>(
        hid_hi, hid_lo, D_MODEL, D_MODEL / QRSPLIT,
        wqa_hi, D_MODEL, D_MODEL / QRSPLIT,
        qrpart, nullptr, nullptr, QLR_, (long long)S_LEN * QLR_,
        D_MODEL / QRSPLIT, 0, nullptr);
    // 4) rms_norm(sum of 4 partials) -> qr_hi/qr_lo
    rmsnorm_split4_kernel<<<S_LEN, 256>>>(
        qrpart, (long long)S_LEN * QLR_, qng, qr_hi, qr_lo, QLR_);
    // 5) q = qr @ wq_b^T with fused RoPE+scale+split -> qhi/qlo
    gemm_f16_pre<<<dim3((NH * DHD) / 128, S_LEN / 128, 1), 256, GEMM_SMEM>>>(
        qr_hi, qr_lo, QLR_, 0, wqb_hi, QLR_, 0,
        nullptr, qhi, qlo, NH * DHD, 0, QLR_, 1, cs);
    // 6) kv reduce + rmsnorm + V^T + RoPE-K (1-term outputs)
    kv_fused_kernel<<<S_LEN, DHD>>>(kvpart, kvng, cs, khi, vthi);
    // 7) attention -> attn_hi/attn_lo
    attn_mma_kernel<<<dim3(S_LEN / 64, NH), 256, ATTN_SMEM>>>(
        qhi, qlo, khi, vthi, sink, attn_hi, attn_lo);
    // 8) grouped wo_a -> low_hi/low_lo (fused split epilogue)
    gemm_f16_pre<<<dim3(OLR_ / 128, S_LEN / 128, NG), 256, GEMM_SMEM>>>(
        attn_hi, attn_lo, NH * DHD, 1024,
        woa_hi, 1024, (long long)OLR_ * 1024,
        nullptr, low_hi, low_lo, NG * OLR_, OLR_, 1024, 0, nullptr);
    // 9) out = low @ wo_b^T
    gemm_f16_pre<<<dim3(D_MODEL / 128, S_LEN / 128, 1), 256, GEMM_SMEM>>>(
        low_hi, low_lo, NG * OLR_, 0, wob_hi, NG * OLR_, 0,
        out, nullptr, nullptr, D_MODEL, 0, NG * OLR_, 0, nullptr);
}

// round 17
// speedup vs baseline: 1.6174x; 1.0596x over previous
#include <cuda_runtime.h>
#include <cuda_fp16.h>

#define S_LEN 2048
#define D_MODEL 4096
#define NH 32
#define DHD 128
#define QLR_ 1536
#define OLR_ 512
#define NG 4
#define QRSPLIT 4
#define NCOMB (QLR_ + DHD)          // 1664 combined qr+kv output cols
#define QK_SCALE 0.08838834764831845f

typedef __half hf;

// ---------------- scratch (no allocation allowed -> device globals) ---------
__device__ float g_qrkvpart[QRSPLIT * S_LEN * NCOMB];
__device__ float g_cs[S_LEN * 32 * 2];

__device__ hf g_qhi[S_LEN * NH * DHD], g_qlo[S_LEN * NH * DHD];
__device__ hf g_khi[S_LEN * DHD];
__device__ hf g_vthi[DHD * S_LEN];                 // transposed V (1-term)

__device__ hf g_hid_hi[S_LEN * D_MODEL],  g_hid_lo[S_LEN * D_MODEL];
__device__ hf g_wqakv_hi[NCOMB * D_MODEL];         // [wq_a ; wkv] along N
__device__ hf g_wqb_hi[NH * DHD * QLR_];
__device__ hf g_qr_hi[S_LEN * QLR_],      g_qr_lo[S_LEN * QLR_];
__device__ hf g_attn_hi[S_LEN * NH * DHD],g_attn_lo[S_LEN * NH * DHD];
__device__ hf g_woa_hi[NG * OLR_ * 1024];
__device__ hf g_low_hi[S_LEN * NG * OLR_],g_low_lo[S_LEN * NG * OLR_];
__device__ hf g_wob_hi[D_MODEL * NG * OLR_];

// ---------------- fp16 split helpers ----------------------------------------
__device__ __forceinline__ void f16_split1(float f, hf& h, hf& l)
{
    h = __float2half_rn(f);
    l = __float2half_rn(f - __half2float(h));
}

__device__ __forceinline__ unsigned pack_split_f16(float p0, float p1,
                                                   unsigned& lo)
{
    unsigned hi;
    asm("cvt.rn.f16x2.f32 %0, %1, %2;" : "=r"(hi) : "f"(p1), "f"(p0));
    __half2 hb = *reinterpret_cast<__half2*>(&hi);
    float h0 = __half2float(__low2half(hb));
    float h1 = __half2float(__high2half(hb));
    asm("cvt.rn.f16x2.f32 %0, %1, %2;" : "=r"(lo)
        : "f"(p1 - h1), "f"(p0 - h0));
    return hi;
}

__device__ __forceinline__ unsigned pack_f16(float p0, float p1)
{
    unsigned hi;
    asm("cvt.rn.f16x2.f32 %0, %1, %2;" : "=r"(hi) : "f"(p1), "f"(p0));
    return hi;
}

// ---------------- one-launch segmented operand split ------------------------
struct SplitSeg { const float4* src; uint2* hi; uint2* lo; int n4; int mode; };
struct SplitArgs { SplitSeg seg[6]; };

__global__ void split_multi(SplitArgs a)
{
    const SplitSeg s = a.seg[blockIdx.y];
    int i = blockIdx.x * blockDim.x + threadIdx.x;
    if (i >= s.n4) return;
    float4 v = s.src[i];
    if (s.mode == 0) {
        unsigned l01, l23;
        unsigned h01 = pack_split_f16(v.x, v.y, l01);
        unsigned h23 = pack_split_f16(v.z, v.w, l23);
        s.hi[i] = make_uint2(h01, h23);
        s.lo[i] = make_uint2(l01, l23);
    } else {
        s.hi[i] = make_uint2(pack_f16(v.x, v.y), pack_f16(v.z, v.w));
    }
}

// ---------------- cos/sin table (fp64 once) ---------------------------------
__global__ void cs_table_kernel(float* __restrict__ cs,
                                const void* __restrict__ pos_raw)
{
    const int s = blockIdx.x, d = threadIdx.x;
    const int* p32 = (const int*)pos_raw;
    long long p;
    if (p32[1] == 1) p = (long long)p32[s];
    else             p = ((const long long*)pos_raw)[s];
    const double inv = pow(10000.0, -(double)d / 32.0);
    const double ang = (double)p * inv;
    cs[(s * 32 + d) * 2 + 0] = (float)cos(ang);
    cs[(s * 32 + d) * 2 + 1] = (float)sin(ang);
}

// ============================================================================
// FP16 tensor-core GEMM, 2-term split (A = hi+lo fp16, B = hi fp16 only).
// k32 2-stage cp.async, ldmatrix. C[M,N] = A[M,K] @ B[N,K]^T.
// CTA 128x128x32, 8 warps (2x4), m16n8k16.
// ============================================================================
#define GPW 20
#define GAW (128 * GPW)
#define GEMM_SMEM (2 * 3 * GAW * 4)   // 61440 B (Ah|Al|Bh per stage)

#define MMA_F16(c, a, b)                                                   \
    asm volatile(                                                          \
        "mma.sync.aligned.m16n8k16.row.col.f32.f16.f16.f32 "               \
        "{%0,%1,%2,%3}, {%4,%5,%6,%7}, {%8,%9}, {%0,%1,%2,%3};"            \
        : "+f"((c)[0]), "+f"((c)[1]), "+f"((c)[2]), "+f"((c)[3])           \
        : "r"((a)[0]), "r"((a)[1]), "r"((a)[2]), "r"((a)[3]),              \
          "r"((b)[0]), "r"((b)[1]))

#define LDSM_X4(r, addr)                                                   \
    asm volatile("ldmatrix.sync.aligned.m8n8.x4.shared.b16 "               \
                 "{%0,%1,%2,%3}, [%4];"                                    \
                 : "=r"((r)[0]), "=r"((r)[1]), "=r"((r)[2]), "=r"((r)[3])  \
                 : "r"(addr))

#define CPA16(dst, src)                                                    \
    asm volatile("cp.async.cg.shared.global [%0], [%1], 16;"               \
                 :: "r"(dst), "l"(src))
#define CPA_COMMIT() asm volatile("cp.async.commit_group;" ::)
#define CPA_WAIT1()  asm volatile("cp.async.wait_group 1;" ::)

__global__ void __launch_bounds__(256, 2) gemm_f16_pre(
    const hf* __restrict__ Ahi, const hf* __restrict__ Alo,
    int lda, long long sAz,
    const hf* __restrict__ Bhi,
    int ldb, long long sBz,
    float* __restrict__ C, hf* __restrict__ Chi, hf* __restrict__ Clo,
    int ldc, long long sCz,
    int K, int rope, const float* __restrict__ cst)
{
    extern __shared__ unsigned smw[];
    const size_t zo = (size_t)blockIdx.z;

    const int bm = blockIdx.y * 128;
    const int bn = blockIdx.x * 128;
    const int tid = threadIdx.x;
    const int wid = tid >> 5, lane = tid & 31;
    const int wm = wid & 1, wn = wid >> 1;
    const int gid = lane >> 2, tig = lane & 3;

    const int i0 = tid, i1 = tid + 256;
    const int r0 = i0 >> 2, c0q = i0 & 3;
    const int r1 = i1 >> 2, c1q = i1 & 3;
    const hf* gA0 = Ahi + zo * sAz + (size_t)(bm + r0) * lda + c0q * 8;
    const hf* gA1 = Ahi + zo * sAz + (size_t)(bm + r1) * lda + c1q * 8;
    const hf* gB0 = Bhi + zo * sBz + (size_t)(bn + r0) * ldb + c0q * 8;
    const hf* gB1 = Bhi + zo * sBz + (size_t)(bn + r1) * ldb + c1q * 8;
    const long long dA = Alo - Ahi;

    const unsigned smem0 = (unsigned)__cvta_generic_to_shared(smw);
    const unsigned d0 = (r0 * GPW + c0q * 4) * 4;
    const unsigned d1 = (r1 * GPW + c1q * 4) * 4;
    const unsigned ARR = GAW * 4;

    const int lane15 = lane & 15;
    const unsigned aoff = (unsigned)(((wm * 64 + lane15) * GPW
                          + ((lane >> 4) << 2)) * 4);
    const unsigned boff = (unsigned)(((wn * 32 + (lane & 7)
                          + ((lane >> 4) << 3)) * GPW
                          + (((lane >> 3) & 1) << 2)) * 4);

    float acc[4][4][4];
#pragma unroll
    for (int i = 0; i < 4; i++)
#pragma unroll
        for (int j = 0; j < 4; j++)
#pragma unroll
            for (int l = 0; l < 4; l++) acc[i][j][l] = 0.f;

#define ISSUE_TILE(stage, koff)                                            \
    do {                                                                   \
        unsigned b_ = smem0 + (stage) * 3 * ARR;                           \
        CPA16(b_ + 0 * ARR + d0, gA0 + (koff));                            \
        CPA16(b_ + 0 * ARR + d1, gA1 + (koff));                            \
        CPA16(b_ + 1 * ARR + d0, gA0 + dA + (koff));                       \
        CPA16(b_ + 1 * ARR + d1, gA1 + dA + (koff));                       \
        CPA16(b_ + 2 * ARR + d0, gB0 + (koff));                            \
        CPA16(b_ + 2 * ARR + d1, gB1 + (koff));                            \
    } while (0)

    const int T = K / 32;
    ISSUE_TILE(0, 0);
    CPA_COMMIT();
    ISSUE_TILE(1, 32);
    CPA_COMMIT();
    CPA_WAIT1();
    __syncthreads();

    for (int t = 0; t < T; t++) {
        const int s = t & 1;
        const unsigned base = smem0 + s * 3 * ARR;
        const unsigned aH = base + aoff;
        const unsigned aL = aH + ARR;
        const unsigned bH = base + 2 * ARR + boff;

#pragma unroll
        for (int kk = 0; kk < 2; kk++) {
            const unsigned kb = kk * 32;
            unsigned ah[4][4], al[4][4], bh[2][4];
#pragma unroll
            for (int mf = 0; mf < 4; mf++) {
                LDSM_X4(ah[mf], aH + mf * (16 * GPW * 4) + kb);
                LDSM_X4(al[mf], aL + mf * (16 * GPW * 4) + kb);
            }
#pragma unroll
            for (int p = 0; p < 2; p++)
                LDSM_X4(bh[p], bH + p * (16 * GPW * 4) + kb);
#pragma unroll
            for (int mf = 0; mf < 4; mf++)
#pragma unroll
                for (int nf = 0; nf < 4; nf++) {
                    unsigned bfh[2] = { bh[nf >> 1][(nf & 1) * 2],
                                        bh[nf >> 1][(nf & 1) * 2 + 1] };
                    MMA_F16(acc[mf][nf], ah[mf], bfh);
                    MMA_F16(acc[mf][nf], al[mf], bfh);
                }
        }

        __syncthreads();
        if (t + 2 < T) ISSUE_TILE(s, (t + 2) * 32);
        CPA_COMMIT();
        CPA_WAIT1();
        __syncthreads();
    }

#pragma unroll
    for (int mf = 0; mf < 4; mf++) {
        const int row = bm + wm * 64 + mf * 16 + gid;
#pragma unroll
        for (int nf = 0; nf < 4; nf++) {
            const int col = bn + wn * 32 + nf * 8 + tig * 2;
            const size_t o0 = zo * sCz + (size_t)row * ldc + col;
            const size_t o1 = zo * sCz + (size_t)(row + 8) * ldc + col;
            float v0 = acc[mf][nf][0], v1 = acc[mf][nf][1];
            float w0 = acc[mf][nf][2], w1 = acc[mf][nf][3];
            if (rope) {
                const int dh = col & 127;
                if (dh >= 64) {
                    const int d = (dh - 64) >> 1;
                    const float c0 = cst[(row * 32 + d) * 2];
                    const float s0 = cst[(row * 32 + d) * 2 + 1];
                    const float c1 = cst[((row + 8) * 32 + d) * 2];
                    const float s1 = cst[((row + 8) * 32 + d) * 2 + 1];
                    float t0 = v0 * c0 - v1 * s0;
                    float t1 = v0 * s0 + v1 * c0;
                    v0 = t0; v1 = t1;
                    t0 = w0 * c1 - w1 * s1;
                    t1 = w0 * s1 + w1 * c1;
                    w0 = t0; w1 = t1;
                }
                v0 *= QK_SCALE; v1 *= QK_SCALE;
                w0 *= QK_SCALE; w1 *= QK_SCALE;
            }
            if (C) {
                *reinterpret_cast<float2*>(&C[o0]) = make_float2(v0, v1);
                *reinterpret_cast<float2*>(&C[o1]) = make_float2(w0, w1);
            }
            if (Chi) {
                unsigned lo0, lo1;
                unsigned hi0 = pack_split_f16(v0, v1, lo0);
                unsigned hi1 = pack_split_f16(w0, w1, lo1);
                *reinterpret_cast<unsigned*>(&Chi[o0]) = hi0;
                *reinterpret_cast<unsigned*>(&Clo[o0]) = lo0;
                *reinterpret_cast<unsigned*>(&Chi[o1]) = hi1;
                *reinterpret_cast<unsigned*>(&Clo[o1]) = lo1;
            }
        }
    }
#undef ISSUE_TILE
}

// ------- RMS norm over qr cols of merged partials -> f16 hi/lo --------------
__global__ void rmsnorm_split4_kernel(const float* __restrict__ x,
                                      long long zstride, int ldx,
                                      const float* __restrict__ g,
                                      hf* __restrict__ xhi,
                                      hf* __restrict__ xlo, int N)
{
    const int row = blockIdx.x;
    const float* r0 = x + (size_t)row * ldx;
    float ss = 0.f;
    for (int c = threadIdx.x; c < N; c += blockDim.x) {
        float v = r0[c] + r0[c + zstride] + r0[c + 2 * zstride]
                + r0[c + 3 * zstride];
        ss += v * v;
    }
#pragma unroll
    for (int o = 16; o; o >>= 1) ss += __shfl_xor_sync(0xFFFFFFFFu, ss, o);
    __shared__ float red[32];
    const int w = threadIdx.x >> 5, l = threadIdx.x & 31;
    if (l == 0) red[w] = ss;
    __syncthreads();
    if (threadIdx.x == 0) {
        float t = 0.f;
        int nw = blockDim.x >> 5;
        for (int i = 0; i < nw; i++) t += red[i];
        red[0] = rsqrtf(t / (float)N + 1e-6f);
    }
    __syncthreads();
    const float inv = red[0];
    for (int c = threadIdx.x; c < N; c += blockDim.x) {
        float v = (r0[c] + r0[c + zstride] + r0[c + 2 * zstride]
                 + r0[c + 3 * zstride]) * inv * g[c];
        hf h, lo;
        f16_split1(v, h, lo);
        xhi[(size_t)row * N + c] = h;
        xlo[(size_t)row * N + c] = lo;
    }
}

// -- kv cols of merged partials: reduce + rmsnorm + V^T + RoPE-K (1-term) ----
__global__ void kv_fused_kernel(const float* __restrict__ parts,  // +1536 col
                                long long zstride, int ldx,
                                const float* __restrict__ g,
                                const float* __restrict__ cs,
                                hf* __restrict__ khi,
                                hf* __restrict__ vthi)
{
    const int row = blockIdx.x, tid = threadIdx.x;   // row = s, tid = d
    const float* r0 = parts + (size_t)row * ldx + tid;
    float x = r0[0] + r0[zstride] + r0[2 * zstride] + r0[3 * zstride];
    float ss = x * x;
#pragma unroll
    for (int o = 16; o; o >>= 1) ss += __shfl_xor_sync(0xFFFFFFFFu, ss, o);
    __shared__ float r4[4];
    if ((tid & 31) == 0) r4[tid >> 5] = ss;
    __syncthreads();
    const float tot = r4[0] + r4[1] + r4[2] + r4[3];
    const float v = x * rsqrtf(tot / (float)DHD + 1e-6f) * g[tid];

    vthi[(size_t)tid * S_LEN + row] = __float2half_rn(v);

    const float partner = __shfl_xor_sync(0xFFFFFFFFu, v, 1);
    float kval = v;
    if (tid >= 64) {
        const int dd = (tid - 64) >> 1;
        const float c = cs[(row * 32 + dd) * 2 + 0];
        const float n = cs[(row * 32 + dd) * 2 + 1];
        kval = (tid & 1) ? (partner * n + v * c) : (v * c - partner * n);
    }
    khi[(size_t)row * DHD + tid] = __float2half_rn(kval);
}

// ---------------- FP16 tensor-core flash attention with sink ----------------
// grid (S/64, NH), 256 threads (8 warps: 4 M x 2 N). 64q x 128k tiles.
// Q = 2-term fp16; K, V, P = 1-term. cp.async pipelined, heavy tiles first.
#define QPW 68
#define VPW 68
#define PPW 68
#define ATTN_WORDS (2*64*QPW + 128*QPW + 128*VPW + 64*PPW + 256)
#define ATTN_SMEM (ATTN_WORDS * 4)

__global__ void __launch_bounds__(256) attn_mma_kernel(
    const hf* __restrict__ Qhi, const hf* __restrict__ Qlo,
    const hf* __restrict__ Khi,
    const hf* __restrict__ Vthi,
    const float* __restrict__ sink,
    hf* __restrict__ Ohi, hf* __restrict__ Olo)
{
    extern __shared__ unsigned smw[];
    unsigned* Qh  = smw;
    unsigned* Ql  = Qh + 64 * QPW;
    unsigned* Kh  = Ql + 64 * QPW;
    unsigned* Vth = Kh + 128 * QPW;
    unsigned* Ph  = Vth + 128 * VPW;
    float* smax = (float*)(Ph + 64 * PPW);
    float* ssum = smax + 128;

    const int h  = blockIdx.y;
    const int qt = gridDim.x - 1 - blockIdx.x;   // heavy tiles first
    const int q0 = qt * 64;
    const int tid = threadIdx.x;
    const int w = tid >> 5, lane = tid & 31;
    const int wm = w & 3, wn = w >> 2;
    const int g = lane >> 2, t = lane & 3;
    const int m0 = wm * 16;
    const int rA = m0 + g, rB = m0 + g + 8;

    const unsigned sQh = (unsigned)__cvta_generic_to_shared(Qh);
    const unsigned sQl = (unsigned)__cvta_generic_to_shared(Ql);
    const unsigned sKh = (unsigned)__cvta_generic_to_shared(Kh);
    const unsigned sVh = (unsigned)__cvta_generic_to_shared(Vth);
    const unsigned sPh = (unsigned)__cvta_generic_to_shared(Ph);

    const int lane15 = lane & 15;
    const unsigned qoffA = (unsigned)(((m0 + lane15) * QPW
                           + ((lane >> 4) << 2)) * 4);
    const unsigned koffB = (unsigned)(((wn * 64 + (lane & 7)
                           + ((lane >> 4) << 3)) * QPW
                           + (((lane >> 3) & 1) << 2)) * 4);
    const unsigned poffA = (unsigned)(((m0 + lane15) * PPW
                           + ((lane >> 4) << 2)) * 4);
    const unsigned voffB = (unsigned)(((wn * 64 + (lane & 7)
                           + ((lane >> 4) << 3)) * VPW
                           + (((lane >> 3) & 1) << 2)) * 4);

#define AT_ISSUE_K(k0_)                                                    \
    for (int j = 0; j < 8; j++) {                                          \
        int idx = tid + j * 256;                                           \
        int r_ = idx >> 4, cq_ = idx & 15;                                 \
        unsigned so_ = (r_ * QPW + cq_ * 4) * 4;                           \
        size_t go_ = (size_t)((k0_) + r_) * DHD + cq_ * 8;                 \
        CPA16(sKh + so_, Khi + go_);                                       \
    }
#define AT_ISSUE_V(k0_)                                                    \
    for (int j = 0; j < 8; j++) {                                          \
        int idx = tid + j * 256;                                           \
        int r_ = idx >> 4, cq_ = idx & 15;                                 \
        unsigned so_ = (r_ * VPW + cq_ * 4) * 4;                           \
        size_t go_ = (size_t)r_ * S_LEN + (k0_) + cq_ * 8;                 \
        CPA16(sVh + so_, Vthi + go_);                                      \
    }

    for (int j = 0; j < 4; j++) {
        int idx = tid + j * 256;
        int r = idx >> 4, cq = idx & 15;
        unsigned so = (r * QPW + cq * 4) * 4;
        size_t go = ((size_t)(q0 + r) * NH + h) * DHD + cq * 8;
        CPA16(sQh + so, Qhi + go);
        CPA16(sQl + so, Qlo + go);
    }
    AT_ISSUE_K(0);
    CPA_COMMIT();
    AT_ISSUE_V(0);
    CPA_COMMIT();

    float mr0 = sink[h], mr1 = mr0, lr0 = 1.f, lr1 = 1.f;
    float oa[8][4];
#pragma unroll
    for (int i = 0; i < 8; i++)
#pragma unroll
        for (int j = 0; j < 4; j++) oa[i][j] = 0.f;

    const int NT = (q0 + 64 + 127) >> 7;   // 128-key tiles, causal
    for (int kt = 0; kt < NT; kt++) {
        const int k0 = kt * 128;
        CPA_WAIT1();
        __syncthreads();

        // ---- S = Q K^T over 128 keys (Q 2-term, K 1-term) ----
        float sa[8][4];
#pragma unroll
        for (int i = 0; i < 8; i++)
#pragma unroll
            for (int j = 0; j < 4; j++) sa[i][j] = 0.f;

#pragma unroll
        for (int ks = 0; ks < 8; ks++) {
            const unsigned kb = ks * 32;
            unsigned ah[4], al[4], kh[4][4];
            LDSM_X4(ah, sQh + qoffA + kb);
            LDSM_X4(al, sQl + qoffA + kb);
#pragma unroll
            for (int p = 0; p < 4; p++)
                LDSM_X4(kh[p], sKh + koffB + p * (16 * QPW * 4) + kb);
#pragma unroll
            for (int nt = 0; nt < 8; nt++) {
                unsigned bh[2] = { kh[nt >> 1][(nt & 1) * 2],
                                   kh[nt >> 1][(nt & 1) * 2 + 1] };
                MMA_F16(sa[nt], ah, bh);
                MMA_F16(sa[nt], al, bh);
            }
        }

        // ---- causal mask ----
        const int qi0 = q0 + rA, qi1 = q0 + rB;
#pragma unroll
        for (int nt = 0; nt < 8; nt++) {
            const int kc0 = k0 + wn * 64 + nt * 8 + 2 * t;
            if (kc0     > qi0) sa[nt][0] = -1e30f;
            if (kc0 + 1 > qi0) sa[nt][1] = -1e30f;
            if (kc0     > qi1) sa[nt][2] = -1e30f;
            if (kc0 + 1 > qi1) sa[nt][3] = -1e30f;
        }

        // ---- row max ----
        float rm0 = -1e30f, rm1 = -1e30f;
#pragma unroll
        for (int nt = 0; nt < 8; nt++) {
            rm0 = fmaxf(rm0, fmaxf(sa[nt][0], sa[nt][1]));
            rm1 = fmaxf(rm1, fmaxf(sa[nt][2], sa[nt][3]));
        }
        rm0 = fmaxf(rm0, __shfl_xor_sync(0xFFFFFFFFu, rm0, 1));
        rm0 = fmaxf(rm0, __shfl_xor_sync(0xFFFFFFFFu, rm0, 2));
        rm1 = fmaxf(rm1, __shfl_xor_sync(0xFFFFFFFFu, rm1, 1));
        rm1 = fmaxf(rm1, __shfl_xor_sync(0xFFFFFFFFu, rm1, 2));
        if (t == 0) { smax[wn * 64 + rA] = rm0; smax[wn * 64 + rB] = rm1; }
        __syncthreads();

        const float mn0 = fmaxf(mr0, fmaxf(smax[rA], smax[64 + rA]));
        const float mn1 = fmaxf(mr1, fmaxf(smax[rB], smax[64 + rB]));
        const float alp0 = __expf(mr0 - mn0);
        const float alp1 = __expf(mr1 - mn1);
        mr0 = mn0; mr1 = mn1;

        // ---- p = exp(s - m), 1-term f16 P tile ----
        float ps0 = 0.f, ps1 = 0.f;
#pragma unroll
        for (int nt = 0; nt < 8; nt++) {
            float p0 = __expf(sa[nt][0] - mn0);
            float p1 = __expf(sa[nt][1] - mn0);
            float p2 = __expf(sa[nt][2] - mn1);
            float p3 = __expf(sa[nt][3] - mn1);
            ps0 += p0 + p1;
            ps1 += p2 + p3;
            const int pw = wn * 32 + nt * 4 + t;
            Ph[rA * PPW + pw] = pack_f16(p0, p1);
            Ph[rB * PPW + pw] = pack_f16(p2, p3);
        }
        ps0 += __shfl_xor_sync(0xFFFFFFFFu, ps0, 1);
        ps0 += __shfl_xor_sync(0xFFFFFFFFu, ps0, 2);
        ps1 += __shfl_xor_sync(0xFFFFFFFFu, ps1, 1);
        ps1 += __shfl_xor_sync(0xFFFFFFFFu, ps1, 2);
        if (t == 0) { ssum[wn * 64 + rA] = ps0; ssum[wn * 64 + rB] = ps1; }
        __syncthreads();   // K smem free after this point

        if (kt + 1 < NT) { AT_ISSUE_K(k0 + 128); }
        CPA_COMMIT();

        lr0 = lr0 * alp0 + ssum[rA] + ssum[64 + rA];
        lr1 = lr1 * alp1 + ssum[rB] + ssum[64 + rB];
#pragma unroll
        for (int nt = 0; nt < 8; nt++) {
            oa[nt][0] *= alp0; oa[nt][1] *= alp0;
            oa[nt][2] *= alp1; oa[nt][3] *= alp1;
        }

        CPA_WAIT1();
        __syncthreads();

        // ---- O += P V over 128 keys (P 1-term, V 1-term) ----
#pragma unroll
        for (int ks = 0; ks < 8; ks++) {
            const unsigned kb = ks * 32;
            unsigned ph[4];
            LDSM_X4(ph, sPh + poffA + kb);
#pragma unroll
            for (int ntp = 0; ntp < 4; ntp++) {
                unsigned vh[4];
                LDSM_X4(vh, sVh + voffB + ntp * (16 * VPW * 4) + kb);
#pragma unroll
                for (int hfx = 0; hfx < 2; hfx++) {
                    const int nt = ntp * 2 + hfx;
                    unsigned bh[2] = { vh[hfx * 2], vh[hfx * 2 + 1] };
                    MMA_F16(oa[nt], ph, bh);
                }
            }
        }
        __syncthreads();
        if (kt + 1 < NT) { AT_ISSUE_V(k0 + 128); }
        CPA_COMMIT();
    }

    const float i0v = 1.f / lr0, i1v = 1.f / lr1;
#pragma unroll
    for (int nt = 0; nt < 8; nt++) {
        const int c = wn * 64 + nt * 8 + 2 * t;
        const size_t oA = ((size_t)(q0 + rA) * NH + h) * DHD + c;
        const size_t oB = ((size_t)(q0 + rB) * NH + h) * DHD + c;
        unsigned lo0, lo1;
        unsigned hi0 = pack_split_f16(oa[nt][0] * i0v, oa[nt][1] * i0v, lo0);
        unsigned hi1 = pack_split_f16(oa[nt][2] * i1v, oa[nt][3] * i1v, lo1);
        *reinterpret_cast<unsigned*>(&Ohi[oA]) = hi0;
        *reinterpret_cast<unsigned*>(&Olo[oA]) = lo0;
        *reinterpret_cast<unsigned*>(&Ohi[oB]) = hi1;
        *reinterpret_cast<unsigned*>(&Olo[oB]) = lo1;
    }
#undef AT_ISSUE_K
#undef AT_ISSUE_V
}

// ---------------- launch ----------------------------------------------------
extern "C" void kernel_launch(void* const* d_in, const int* in_sizes, int n_in,
                              void* d_out, int out_size)
{
    (void)in_sizes; (void)n_in; (void)out_size;
    const float* hidden = (const float*)d_in[0];
    const void*  pos    = d_in[1];
    const float* wq_a   = (const float*)d_in[2];
    const float* qng    = (const float*)d_in[3];
    const float* wq_b   = (const float*)d_in[4];
    const float* wkv    = (const float*)d_in[5];
    const float* kvng   = (const float*)d_in[6];
    const float* wo_a   = (const float*)d_in[7];
    const float* wo_b   = (const float*)d_in[8];
    const float* sink   = (const float*)d_in[9];
    float* out = (float*)d_out;

    float *qrkvpart, *cs;
    hf *qhi, *qlo, *khi, *vthi;
    hf *hid_hi, *hid_lo, *wqakv_hi, *wqb_hi;
    hf *qr_hi, *qr_lo, *attn_hi, *attn_lo;
    hf *woa_hi, *low_hi, *low_lo, *wob_hi;
    cudaGetSymbolAddress((void**)&qrkvpart, g_qrkvpart);
    cudaGetSymbolAddress((void**)&cs,  g_cs);
    cudaGetSymbolAddress((void**)&qhi, g_qhi);
    cudaGetSymbolAddress((void**)&qlo, g_qlo);
    cudaGetSymbolAddress((void**)&khi, g_khi);
    cudaGetSymbolAddress((void**)&vthi, g_vthi);
    cudaGetSymbolAddress((void**)&hid_hi, g_hid_hi);
    cudaGetSymbolAddress((void**)&hid_lo, g_hid_lo);
    cudaGetSymbolAddress((void**)&wqakv_hi, g_wqakv_hi);
    cudaGetSymbolAddress((void**)&wqb_hi, g_wqb_hi);
    cudaGetSymbolAddress((void**)&qr_hi,  g_qr_hi);
    cudaGetSymbolAddress((void**)&qr_lo,  g_qr_lo);
    cudaGetSymbolAddress((void**)&attn_hi, g_attn_hi);
    cudaGetSymbolAddress((void**)&attn_lo, g_attn_lo);
    cudaGetSymbolAddress((void**)&woa_hi, g_woa_hi);
    cudaGetSymbolAddress((void**)&low_hi, g_low_hi);
    cudaGetSymbolAddress((void**)&low_lo, g_low_lo);
    cudaGetSymbolAddress((void**)&wob_hi, g_wob_hi);

    cudaFuncSetAttribute(gemm_f16_pre,
                         cudaFuncAttributeMaxDynamicSharedMemorySize, GEMM_SMEM);
    cudaFuncSetAttribute(attn_mma_kernel,
                         cudaFuncAttributeMaxDynamicSharedMemorySize, ATTN_SMEM);

    // 0) cos/sin table (fp64 once)
    cs_table_kernel<<<S_LEN, 32>>>(cs, pos);

    // 1) one-launch split: activations 2-term, weights 1-term.
    //    wq_a -> combined[0:1536], wkv -> combined[1536:1664] (N-concat).
    SplitArgs sa;
    sa.seg[0] = { (const float4*)hidden, (uint2*)hid_hi, (uint2*)hid_lo,
                  S_LEN * D_MODEL / 4, 0 };
    sa.seg[1] = { (const float4*)wq_a, (uint2*)wqakv_hi, nullptr,
                  QLR_ * D_MODEL / 4, 1 };
    sa.seg[2] = { (const float4*)wkv,
                  (uint2*)(wqakv_hi + (size_t)QLR_ * D_MODEL), nullptr,
                  DHD * D_MODEL / 4, 1 };
    sa.seg[3] = { (const float4*)wq_b, (uint2*)wqb_hi, nullptr,
                  NH * DHD * QLR_ / 4, 1 };
    sa.seg[4] = { (const float4*)wo_a, (uint2*)woa_hi, nullptr,
                  NG * OLR_ * 1024 / 4, 1 };
    sa.seg[5] = { (const float4*)wo_b, (uint2*)wob_hi, nullptr,
                  D_MODEL * NG * OLR_ / 4, 1 };
    split_multi<<<dim3((S_LEN * D_MODEL / 4 + 255) / 256, 6), 256>>>(sa);

    // 2) merged qr+kv partials (split-K by 4): [4][2048][1664]
    gemm_f16_pre<<<dim3(NCOMB / 128, S_LEN / 128, QRSPLIT), 256, GEMM_SMEM>>>(
        hid_hi, hid_lo, D_MODEL, D_MODEL / QRSPLIT,
        wqakv_hi, D_MODEL, D_MODEL / QRSPLIT,
        qrkvpart, nullptr, nullptr, NCOMB, (long long)S_LEN * NCOMB,
        D_MODEL / QRSPLIT, 0, nullptr);
    // 3) rms_norm over qr cols -> qr_hi/qr_lo
    rmsnorm_split4_kernel<<<S_LEN, 256>>>(
        qrkvpart, (long long)S_LEN * NCOMB, NCOMB, qng, qr_hi, qr_lo, QLR_);
    // 4) kv cols: reduce + rmsnorm + V^T + RoPE-K
    kv_fused_kernel<<<S_LEN, DHD>>>(
        qrkvpart + QLR_, (long long)S_LEN * NCOMB, NCOMB, kvng, cs, khi, vthi);
    // 5) q = qr @ wq_b^T with fused RoPE+scale+split -> qhi/qlo
    gemm_f16_pre<<<dim3((NH * DHD) / 128, S_LEN / 128, 1), 256, GEMM_SMEM>>>(
        qr_hi, qr_lo, QLR_, 0, wqb_hi, QLR_, 0,
        nullptr, qhi, qlo, NH * DHD, 0, QLR_, 1, cs);
    // 6) attention -> attn_hi/attn_lo
    attn_mma_kernel<<<dim3(S_LEN / 64, NH), 256, ATTN_SMEM>>>(
        qhi, qlo, khi, vthi, sink, attn_hi, attn_lo);
    // 7) grouped wo_a -> low_hi/low_lo (fused split epilogue)
    gemm_f16_pre<<<dim3(OLR_ / 128, S_LEN / 128, NG), 256, GEMM_SMEM>>>(
        attn_hi, attn_lo, NH * DHD, 1024,
        woa_hi, 1024, (long long)OLR_ * 1024,
        nullptr, low_hi, low_lo, NG * OLR_, OLR_, 1024, 0, nullptr);
    // 8) out = low @ wo_b^T
    gemm_f16_pre<<<dim3(D_MODEL / 128, S_LEN / 128, 1), 256, GEMM_SMEM>>>(
        low_hi, low_lo, NG * OLR_, 0, wob_hi, NG * OLR_, 0,
        out, nullptr, nullptr, D_MODEL, 0, NG * OLR_, 0, nullptr);
}